// round 1
// baseline (speedup 1.0000x reference)
#include <cuda_runtime.h>
#include <math.h>

#define Bb 32
#define Nn 512
#define Vv 5
#define Dd 256
#define Hh 4
#define BN (Bb*Nn)            // 16384 real nodes
#define Tt (BN + Bb*Vv)       // 16544 total nodes
#define HD (Hh*Dd)            // 1024

// -------- scratch (static device memory; no allocations) --------
__device__ float d_all[Tt*Dd];            // all_nodes        [T,256]
__device__ float d_h[(size_t)Tt*HD];      // GAT pre-act      [T,1024]
__device__ float d_asrc[Tt*Hh];           // att scores src   [T,4]
__device__ float d_adst[Tt*Hh];           // att scores dst   [T,4]
__device__ float d_vout[Bb*Vv*Hh*Dd];     // virtual GAT out  [160,4,256]
__device__ float d_g1[Tt*Dd];             // after norm1      [T,256]
__device__ float d_xw[Tt*Dd];             // g1 @ gcn_W       [T,256]
__device__ float d_S[Bb*Dd];              // per-batch sum of virtual xw

// ----------------------------------------------------------------
// K0: build all_nodes = concat(x, tile(virtual_nodes, B))
__global__ void k_build(const float* __restrict__ x, const float* __restrict__ vn) {
    int idx = blockIdx.x * blockDim.x + threadIdx.x;
    if (idx >= Tt * Dd) return;
    int t = idx >> 8;
    int c = idx & 255;
    d_all[idx] = (t < BN) ? x[idx] : vn[((t - BN) % Vv) * Dd + c];
}

// ----------------------------------------------------------------
// Tiled fp32 SGEMM: C[M,N] = A[M,K] * B[K,N], row-major.
// 128x128 block tile, BK=16, 256 threads, 8x8 microtile.
__global__ void __launch_bounds__(256, 2)
k_sgemm(const float* __restrict__ A, const float* __restrict__ Bm,
        float* __restrict__ C, int M, int N, int K) {
    __shared__ float As[16][128];   // [k][m] (transposed)
    __shared__ float Bs[16][128];   // [k][n]

    const int tid = threadIdx.x;
    const int tx = tid & 15;        // 0..15 -> col group
    const int ty = tid >> 4;        // 0..15 -> row group
    const int rowBase = blockIdx.y * 128;
    const int colBase = blockIdx.x * 128;

    float acc[8][8];
#pragma unroll
    for (int i = 0; i < 8; i++)
#pragma unroll
        for (int j = 0; j < 8; j++) acc[i][j] = 0.f;

    for (int kb = 0; kb < K; kb += 16) {
        // load A tile: 128 rows x 16 cols = 512 float4, 2 per thread
#pragma unroll
        for (int q = 0; q < 2; q++) {
            int lin = tid + q * 256;        // 0..511
            int ar = lin >> 2;              // row in tile (0..127)
            int ac = (lin & 3) << 2;        // k offset (0,4,8,12)
            int grow = rowBase + ar;
            float4 v;
            if (grow < M)
                v = *reinterpret_cast<const float4*>(&A[(size_t)grow * K + kb + ac]);
            else
                v = make_float4(0.f, 0.f, 0.f, 0.f);
            As[ac + 0][ar] = v.x;
            As[ac + 1][ar] = v.y;
            As[ac + 2][ar] = v.z;
            As[ac + 3][ar] = v.w;
        }
        // load B tile: 16 rows x 128 cols = 512 float4, 2 per thread
#pragma unroll
        for (int q = 0; q < 2; q++) {
            int lin = tid + q * 256;
            int br = lin >> 5;              // 0..15
            int bc = (lin & 31) << 2;       // 0..124
            float4 v = *reinterpret_cast<const float4*>(
                &Bm[(size_t)(kb + br) * N + colBase + bc]);
            *reinterpret_cast<float4*>(&Bs[br][bc]) = v;
        }
        __syncthreads();

#pragma unroll
        for (int k = 0; k < 16; k++) {
            float a[8], b[8];
#pragma unroll
            for (int i = 0; i < 8; i++) a[i] = As[k][ty * 8 + i];
#pragma unroll
            for (int j = 0; j < 8; j++) b[j] = Bs[k][tx * 8 + j];
#pragma unroll
            for (int i = 0; i < 8; i++)
#pragma unroll
                for (int j = 0; j < 8; j++) acc[i][j] += a[i] * b[j];
        }
        __syncthreads();
    }

#pragma unroll
    for (int i = 0; i < 8; i++) {
        int grow = rowBase + ty * 8 + i;
        if (grow >= M) continue;
        float* cp = &C[(size_t)grow * N + colBase + tx * 8];
#pragma unroll
        for (int j = 0; j < 8; j += 4) {
            float4 v = make_float4(acc[i][j], acc[i][j + 1], acc[i][j + 2], acc[i][j + 3]);
            *reinterpret_cast<float4*>(cp + j) = v;
        }
    }
}

// ----------------------------------------------------------------
// K2: attention scores a_src[t,h] = <h[t,h,:], att_src[h,:]>, same for dst.
// One block per node t; 8 warps = 4 heads x {src,dst}.
__global__ void k_att(const float* __restrict__ att_src, const float* __restrict__ att_dst) {
    int t = blockIdx.x;
    int w = threadIdx.x >> 5;
    int lane = threadIdx.x & 31;
    int head = w >> 1;
    bool is_dst = (w & 1);
    const float* hp = d_h + (size_t)t * HD + head * Dd;
    const float* ap = (is_dst ? att_dst : att_src) + head * Dd;
    float s = 0.f;
#pragma unroll
    for (int j = 0; j < 8; j++) s += hp[lane + 32 * j] * ap[lane + 32 * j];
#pragma unroll
    for (int o = 16; o; o >>= 1) s += __shfl_xor_sync(0xffffffffu, s, o);
    if (lane == 0) {
        if (is_dst) d_adst[t * Hh + head] = s;
        else        d_asrc[t * Hh + head] = s;
    }
}

__device__ __forceinline__ float lrelu(float x) { return x > 0.f ? x : 0.2f * x; }

// ----------------------------------------------------------------
// K3: virtual-node attention softmax + weighted aggregation.
// One block per (batch, head): 128 blocks x 256 threads.
__global__ void k_vagg() {
    int b = blockIdx.x >> 2;
    int head = blockIdx.x & 3;
    int tid = threadIdx.x;

    __shared__ float asrc_sh[Nn];
    __shared__ float w_sh[Vv][Nn + 1];  // [v][0..511]=real weights, [v][512]=self
    __shared__ float red[256];

    for (int i = tid; i < Nn; i += 256)
        asrc_sh[i] = d_asrc[(b * Nn + i) * Hh + head];
    __syncthreads();

    for (int v = 0; v < Vv; v++) {
        int vt = BN + b * Vv + v;
        float adst = d_adst[vt * Hh + head];
        float aself = lrelu(d_asrc[vt * Hh + head] + adst);

        // max over 513 alphas
        float lm = aself;
        for (int i = tid; i < Nn; i += 256) lm = fmaxf(lm, lrelu(asrc_sh[i] + adst));
        red[tid] = lm;
        __syncthreads();
        for (int s = 128; s > 0; s >>= 1) {
            if (tid < s) red[tid] = fmaxf(red[tid], red[tid + s]);
            __syncthreads();
        }
        float m = red[0];
        __syncthreads();

        // exp + sum
        float ls = 0.f;
        for (int i = tid; i < Nn; i += 256) {
            float e = expf(lrelu(asrc_sh[i] + adst) - m);
            w_sh[v][i] = e;
            ls += e;
        }
        float eS = expf(aself - m);
        if (tid == 0) ls += eS;
        red[tid] = ls;
        __syncthreads();
        for (int s = 128; s > 0; s >>= 1) {
            if (tid < s) red[tid] += red[tid + s];
            __syncthreads();
        }
        float inv = 1.f / red[0];
        __syncthreads();

        for (int i = tid; i < Nn; i += 256) w_sh[v][i] *= inv;
        if (tid == 0) w_sh[v][Nn] = eS * inv;
        __syncthreads();
    }

    // aggregation: thread c accumulates Σ_i w[v][i] * h[real_i, head, c]
    int c = tid;
    float acc[Vv] = {0.f, 0.f, 0.f, 0.f, 0.f};
    const size_t hb = (size_t)(b * Nn) * HD + head * Dd;
    for (int i = 0; i < Nn; i++) {
        float hv = d_h[hb + (size_t)i * HD + c];
#pragma unroll
        for (int v = 0; v < Vv; v++) acc[v] += w_sh[v][i] * hv;
    }
#pragma unroll
    for (int v = 0; v < Vv; v++) {
        int vt = BN + b * Vv + v;
        float hself = d_h[(size_t)vt * HD + head * Dd + c];
        acc[v] += w_sh[v][Nn] * hself;
        d_vout[((b * Vv + v) * Hh + head) * Dd + c] = acc[v];
    }
}

// ----------------------------------------------------------------
__device__ __forceinline__ float gelu_exact(float x) {
    return 0.5f * x * (1.f + erff(x * 0.70710678118654752f));
}

__device__ __forceinline__ float block_sum(float v, float* red) {
    int c = threadIdx.x;
    red[c] = v;
    __syncthreads();
    for (int s = 128; s > 0; s >>= 1) {
        if (c < s) red[c] += red[c + s];
        __syncthreads();
    }
    float r = red[0];
    __syncthreads();
    return r;
}

// K4: head-mean + bias + gelu + layernorm1 -> g1. One block per node.
__global__ void k_norm1(const float* __restrict__ gat_bias,
                        const float* __restrict__ g, const float* __restrict__ bta) {
    __shared__ float red[256];
    int t = blockIdx.x;
    int c = threadIdx.x;
    float s;
    if (t < BN) {
        const float* hp = d_h + (size_t)t * HD;
        s = 0.25f * (hp[c] + hp[Dd + c] + hp[2 * Dd + c] + hp[3 * Dd + c]);
    } else {
        const float* vp = d_vout + (size_t)(t - BN) * Hh * Dd;
        s = 0.25f * (vp[c] + vp[Dd + c] + vp[2 * Dd + c] + vp[3 * Dd + c]);
    }
    s += gat_bias[c];
    float ge = gelu_exact(s);
    float mean = block_sum(ge, red) * (1.f / Dd);
    float dlt = ge - mean;
    float var = block_sum(dlt * dlt, red) * (1.f / Dd);
    d_g1[(size_t)t * Dd + c] = dlt * rsqrtf(var + 1e-5f) * g[c] + bta[c];
}

// K6: per-batch sum of virtual-node xw rows.
__global__ void k_vsum() {
    int b = blockIdx.x;
    int c = threadIdx.x;
    float s = 0.f;
#pragma unroll
    for (int v = 0; v < Vv; v++)
        s += d_xw[(size_t)(BN + b * Vv + v) * Dd + c];
    d_S[b * Dd + c] = s;
}

// K7: GCN combine + bias + gelu + layernorm2 -> out (real rows only).
__global__ void k_final(const float* __restrict__ gcn_bias,
                        const float* __restrict__ g, const float* __restrict__ bta,
                        float* __restrict__ out) {
    __shared__ float red[256];
    int t = blockIdx.x;             // real node
    int c = threadIdx.x;
    int b = t / Nn;
    const float inv_sqrt6 = 0.40824829046386301637f;
    const float inv6 = 0.16666666666666666667f;
    float u = inv_sqrt6 * d_S[b * Dd + c] + inv6 * d_xw[(size_t)t * Dd + c] + gcn_bias[c];
    float ge = gelu_exact(u);
    float mean = block_sum(ge, red) * (1.f / Dd);
    float dlt = ge - mean;
    float var = block_sum(dlt * dlt, red) * (1.f / Dd);
    out[(size_t)t * Dd + c] = dlt * rsqrtf(var + 1e-5f) * g[c] + bta[c];
}

// ----------------------------------------------------------------
extern "C" void kernel_launch(void* const* d_in, const int* in_sizes, int n_in,
                              void* d_out, int out_size) {
    const float* x        = (const float*)d_in[0];
    // d_in[1] = edge_index (unused by the reference computation)
    const float* vn       = (const float*)d_in[2];
    const float* gat_W    = (const float*)d_in[3];
    const float* att_src  = (const float*)d_in[4];
    const float* att_dst  = (const float*)d_in[5];
    const float* gat_bias = (const float*)d_in[6];
    const float* gcn_W    = (const float*)d_in[7];
    const float* gcn_bias = (const float*)d_in[8];
    const float* n1g      = (const float*)d_in[9];
    const float* n1b      = (const float*)d_in[10];
    const float* n2g      = (const float*)d_in[11];
    const float* n2b      = (const float*)d_in[12];
    float* out = (float*)d_out;

    float *p_all, *p_h, *p_g1, *p_xw;
    cudaGetSymbolAddress((void**)&p_all, d_all);
    cudaGetSymbolAddress((void**)&p_h,   d_h);
    cudaGetSymbolAddress((void**)&p_g1,  d_g1);
    cudaGetSymbolAddress((void**)&p_xw,  d_xw);

    k_build<<<(Tt * Dd + 255) / 256, 256>>>(x, vn);

    dim3 gemm1(HD / 128, (Tt + 127) / 128);
    k_sgemm<<<gemm1, 256>>>(p_all, gat_W, p_h, Tt, HD, Dd);

    k_att<<<Tt, 256>>>(att_src, att_dst);
    k_vagg<<<Bb * Hh, 256>>>();
    k_norm1<<<Tt, 256>>>(gat_bias, n1g, n1b);

    dim3 gemm2(Dd / 128, (Tt + 127) / 128);
    k_sgemm<<<gemm2, 256>>>(p_g1, gcn_W, p_xw, Tt, Dd, Dd);

    k_vsum<<<Bb, 256>>>();
    k_final<<<BN, 256>>>(gcn_bias, n2g, n2b, out);
}

// round 3
// speedup vs baseline: 1.5435x; 1.5435x over previous
#include <cuda_runtime.h>
#include <cuda_bf16.h>
#include <math.h>
#include <stdint.h>

#define Bb 32
#define Nn 512
#define Vv 5
#define Dd 256
#define Hh 4
#define BN (Bb*Nn)            // 16384 real nodes
#define Tt (BN + Bb*Vv)       // 16544 total nodes
#define TP 16640              // padded to 130*128 rows
#define HD (Hh*Dd)            // 1024
#define Kk 256

// ---------------- scratch (static device memory; zero-initialized) ----------
__device__ __nv_bfloat16 d_Ahi[(size_t)TP*Kk];
__device__ __nv_bfloat16 d_Alo[(size_t)TP*Kk];
__device__ __nv_bfloat16 d_B1hi[HD*Kk];   // gat_W^T  [1024,256]
__device__ __nv_bfloat16 d_B1lo[HD*Kk];
__device__ __nv_bfloat16 d_B2hi[Dd*Kk];   // gcn_W^T  [256,256]
__device__ __nv_bfloat16 d_B2lo[Dd*Kk];
__device__ float d_h[(size_t)TP*HD];      // GAT pre-act [TP,1024] fp32
__device__ float d_asrc[Tt*Hh];
__device__ float d_adst[Tt*Hh];
__device__ float d_w[128*Vv*520];         // softmax weights [bh][v][513]
__device__ float d_vpart[8*128*Vv*Dd];    // chunked virtual aggregation partials
__device__ __nv_bfloat16 d_G1hi[(size_t)TP*Kk];
__device__ __nv_bfloat16 d_G1lo[(size_t)TP*Kk];
__device__ float d_xw[(size_t)TP*Dd];
__device__ float d_S[Bb*Dd];

// ---------------- helpers ----------------------------------------------
__device__ __forceinline__ uint32_t smem_u32(const void* p) {
    uint32_t a;
    asm("{ .reg .u64 t; cvta.to.shared.u64 t, %1; cvt.u32.u64 %0, t; }"
        : "=r"(a) : "l"(p));
    return a;
}
// 64B-row XOR swizzle: toggles byte bits [5:4] with row bits [2:1]
__device__ __forceinline__ uint32_t sw64(uint32_t off) { return off ^ ((off >> 3) & 0x30); }

__device__ __forceinline__ void ldmx4(uint32_t* r, uint32_t addr) {
    asm volatile("ldmatrix.sync.aligned.m8n8.x4.shared.b16 {%0,%1,%2,%3}, [%4];"
                 : "=r"(r[0]), "=r"(r[1]), "=r"(r[2]), "=r"(r[3]) : "r"(addr));
}
__device__ __forceinline__ void mma16816(float* d, const uint32_t* a, uint32_t b0, uint32_t b1) {
    asm volatile(
        "mma.sync.aligned.m16n8k16.row.col.f32.bf16.bf16.f32 "
        "{%0,%1,%2,%3}, {%4,%5,%6,%7}, {%8,%9}, {%0,%1,%2,%3};"
        : "+f"(d[0]), "+f"(d[1]), "+f"(d[2]), "+f"(d[3])
        : "r"(a[0]), "r"(a[1]), "r"(a[2]), "r"(a[3]), "r"(b0), "r"(b1));
}

__device__ __forceinline__ void split_bf16(float v, __nv_bfloat16& hi, __nv_bfloat16& lo) {
    hi = __float2bfloat16(v);
    lo = __float2bfloat16(v - __bfloat162float(hi));
}

// ---------------- split builders -----------------------------------------
// all_nodes = concat(x, tile(virtual,B)) as bf16 hi/lo
__global__ void k_build_split(const float* __restrict__ x, const float* __restrict__ vn) {
    int idx = blockIdx.x * 256 + threadIdx.x;   // < Tt*Dd
    int t = idx >> 8;
    int c = idx & 255;
    float v = (t < BN) ? x[idx] : vn[((t - BN) % Vv) * Dd + c];
    __nv_bfloat16 hi, lo;
    split_bf16(v, hi, lo);
    d_Ahi[idx] = hi;
    d_Alo[idx] = lo;
}

// transpose + split:  B [K=256, N] fp32 -> Bt [N, 256] bf16 hi/lo
__global__ void k_cvt_bt(const float* __restrict__ B, int N,
                         __nv_bfloat16* __restrict__ Bthi, __nv_bfloat16* __restrict__ Btlo) {
    int idx = blockIdx.x * 256 + threadIdx.x;   // idx = n*256 + k
    int n = idx >> 8;
    int k = idx & 255;
    float v = B[k * N + n];
    __nv_bfloat16 hi, lo;
    split_bf16(v, hi, lo);
    Bthi[idx] = hi;
    Btlo[idx] = lo;
}

// ---------------- mma.sync split-bf16 GEMM ---------------------------------
// C[TP, Ncols] = A[TP,256] * Bt[Ncols,256]^T, fp32 out.
// grid (Ncols/128, TP/128), 256 threads (8 warps = 2m x 4n), warp 64x32.
__global__ void __launch_bounds__(256, 1) k_mma_gemm(
    const __nv_bfloat16* __restrict__ Ahi, const __nv_bfloat16* __restrict__ Alo,
    const __nv_bfloat16* __restrict__ Bhi, const __nv_bfloat16* __restrict__ Blo,
    float* __restrict__ C, int Ncols)
{
    __shared__ __align__(128) __nv_bfloat16 sAh[128 * 32];
    __shared__ __align__(128) __nv_bfloat16 sAl[128 * 32];
    __shared__ __align__(128) __nv_bfloat16 sBh[128 * 32];
    __shared__ __align__(128) __nv_bfloat16 sBl[128 * 32];

    const int tid = threadIdx.x;
    const int wid = tid >> 5, lane = tid & 31;
    const int wm = (wid >> 2) * 64;     // warp m offset (0 or 64)
    const int wn = (wid & 3) * 32;      // warp n offset
    const int mBase = blockIdx.y * 128;
    const int nBase = blockIdx.x * 128;

    const uint32_t sAhB = smem_u32(sAh), sAlB = smem_u32(sAl);
    const uint32_t sBhB = smem_u32(sBh), sBlB = smem_u32(sBl);

    const uint4* A4h = reinterpret_cast<const uint4*>(Ahi);
    const uint4* A4l = reinterpret_cast<const uint4*>(Alo);
    const uint4* B4h = reinterpret_cast<const uint4*>(Bhi);
    const uint4* B4l = reinterpret_cast<const uint4*>(Blo);

    float acc[4][4][4];
#pragma unroll
    for (int i = 0; i < 4; i++)
#pragma unroll
        for (int j = 0; j < 4; j++)
#pragma unroll
            for (int e = 0; e < 4; e++) acc[i][j][e] = 0.f;

    // ldmatrix lane address components (byte offsets within smem tiles)
    // A tile (16x16 at (mt, s)): row = wm + mt*16 + (lane&7) + (lane&8), colB = s*32 + ((lane&16)?16:0)
    const uint32_t aRow = (uint32_t)((lane & 7) + (lane & 8));
    const uint32_t aColB = (lane & 16) ? 16u : 0u;
    // B tile (n16 x k16 at (ng, s)): row = wn + ng*16 + (lane&7) + ((lane&16)>>1), colB = s*32 + ((lane&8)?16:0)
    const uint32_t bRow = (uint32_t)((lane & 7) + ((lane & 16) >> 1));
    const uint32_t bColB = (lane & 8) ? 16u : 0u;

    for (int kc = 0; kc < 8; kc++) {   // 8 chunks of K=32
        // ---- load 4 tiles of 128 rows x 64B ----
#pragma unroll
        for (int q = 0; q < 2; q++) {
            int lin = tid + q * 256;        // 0..511
            int row = lin >> 2;             // 0..127
            int c16 = lin & 3;
            uint32_t sw = sw64((uint32_t)(row * 64 + c16 * 16));
            int ga = (mBase + row) * 32 + kc * 4 + c16;   // uint4 idx (32 per 256-bf16 row)
            int gb = (nBase + row) * 32 + kc * 4 + c16;
            *reinterpret_cast<uint4*>(reinterpret_cast<char*>(sAh) + sw) = A4h[ga];
            *reinterpret_cast<uint4*>(reinterpret_cast<char*>(sAl) + sw) = A4l[ga];
            *reinterpret_cast<uint4*>(reinterpret_cast<char*>(sBh) + sw) = B4h[gb];
            *reinterpret_cast<uint4*>(reinterpret_cast<char*>(sBl) + sw) = B4l[gb];
        }
        __syncthreads();

        // ---- compute: 2 k-steps of 16 ----
#pragma unroll
        for (int s = 0; s < 2; s++) {
            uint32_t ah[4][4], al[4][4], bh[2][4], bl[2][4];
#pragma unroll
            for (int mt = 0; mt < 4; mt++) {
                uint32_t byteo = sw64((uint32_t)((wm + mt * 16 + aRow) * 64) + s * 32u + aColB);
                ldmx4(ah[mt], sAhB + byteo);
                ldmx4(al[mt], sAlB + byteo);
            }
#pragma unroll
            for (int ng = 0; ng < 2; ng++) {
                uint32_t byteo = sw64((uint32_t)((wn + ng * 16 + bRow) * 64) + s * 32u + bColB);
                ldmx4(bh[ng], sBhB + byteo);
                ldmx4(bl[ng], sBlB + byteo);
            }
#pragma unroll
            for (int mt = 0; mt < 4; mt++)
#pragma unroll
                for (int ng = 0; ng < 2; ng++) {
                    mma16816(acc[mt][ng * 2],     ah[mt], bh[ng][0], bh[ng][1]);
                    mma16816(acc[mt][ng * 2 + 1], ah[mt], bh[ng][2], bh[ng][3]);
                    mma16816(acc[mt][ng * 2],     ah[mt], bl[ng][0], bl[ng][1]);
                    mma16816(acc[mt][ng * 2 + 1], ah[mt], bl[ng][2], bl[ng][3]);
                    mma16816(acc[mt][ng * 2],     al[mt], bh[ng][0], bh[ng][1]);
                    mma16816(acc[mt][ng * 2 + 1], al[mt], bh[ng][2], bh[ng][3]);
                }
        }
        __syncthreads();
    }

    // ---- epilogue ----
    int mThr = mBase + wm + (lane >> 2);
    int nThr = nBase + wn + (lane & 3) * 2;
#pragma unroll
    for (int mt = 0; mt < 4; mt++)
#pragma unroll
        for (int nt = 0; nt < 4; nt++) {
            int r0 = mThr + mt * 16;
            int cc = nThr + nt * 8;
            float2 v0 = make_float2(acc[mt][nt][0], acc[mt][nt][1]);
            float2 v1 = make_float2(acc[mt][nt][2], acc[mt][nt][3]);
            *reinterpret_cast<float2*>(C + (size_t)r0 * Ncols + cc) = v0;
            *reinterpret_cast<float2*>(C + (size_t)(r0 + 8) * Ncols + cc) = v1;
        }
}

// ---------------- attention scores ------------------------------------------
__global__ void k_att(const float* __restrict__ att_src, const float* __restrict__ att_dst) {
    int t = blockIdx.x;
    int w = threadIdx.x >> 5;
    int lane = threadIdx.x & 31;
    int head = w >> 1;
    bool is_dst = (w & 1);
    const float* hp = d_h + (size_t)t * HD + head * Dd;
    const float* ap = (is_dst ? att_dst : att_src) + head * Dd;
    float s = 0.f;
#pragma unroll
    for (int j = 0; j < 8; j++) s += hp[lane + 32 * j] * ap[lane + 32 * j];
#pragma unroll
    for (int o = 16; o; o >>= 1) s += __shfl_xor_sync(0xffffffffu, s, o);
    if (lane == 0) {
        if (is_dst) d_adst[t * Hh + head] = s;
        else        d_asrc[t * Hh + head] = s;
    }
}

__device__ __forceinline__ float lrelu(float x) { return x > 0.f ? x : 0.2f * x; }

// ---------------- softmax weights (per batch,head) --------------------------
__global__ void k_vw() {
    int bh = blockIdx.x;               // 0..127
    int b = bh >> 2, head = bh & 3;
    int tid = threadIdx.x;

    __shared__ float asrc_sh[Nn];
    __shared__ float e_sh[Nn];
    __shared__ float red[256];

    for (int i = tid; i < Nn; i += 256)
        asrc_sh[i] = d_asrc[(b * Nn + i) * Hh + head];
    __syncthreads();

    for (int v = 0; v < Vv; v++) {
        int vt = BN + b * Vv + v;
        float adst = d_adst[vt * Hh + head];
        float aself = lrelu(d_asrc[vt * Hh + head] + adst);

        float lm = aself;
        for (int i = tid; i < Nn; i += 256) lm = fmaxf(lm, lrelu(asrc_sh[i] + adst));
        red[tid] = lm;
        __syncthreads();
        for (int s = 128; s > 0; s >>= 1) {
            if (tid < s) red[tid] = fmaxf(red[tid], red[tid + s]);
            __syncthreads();
        }
        float m = red[0];
        __syncthreads();

        float ls = 0.f;
        for (int i = tid; i < Nn; i += 256) {
            float e = expf(lrelu(asrc_sh[i] + adst) - m);
            e_sh[i] = e;
            ls += e;
        }
        float eS = expf(aself - m);
        if (tid == 0) ls += eS;
        red[tid] = ls;
        __syncthreads();
        for (int s = 128; s > 0; s >>= 1) {
            if (tid < s) red[tid] += red[tid + s];
            __syncthreads();
        }
        float inv = 1.f / red[0];
        __syncthreads();

        float* wp = d_w + (size_t)(bh * Vv + v) * 520;
        for (int i = tid; i < Nn; i += 256) wp[i] = e_sh[i] * inv;
        if (tid == 0) wp[512] = eS * inv;
        __syncthreads();
    }
}

// ---------------- chunked virtual aggregation -------------------------------
// grid (128, 8): (batch*head, i-chunk of 64). block 256 = channel.
__global__ void k_vagg2() {
    int bh = blockIdx.x;
    int chunk = blockIdx.y;
    int b = bh >> 2, head = bh & 3;
    int c = threadIdx.x;

    __shared__ float w_sh[Vv][64];
    for (int idx = c; idx < Vv * 64; idx += 256) {
        int v = idx >> 6, ii = idx & 63;
        w_sh[v][ii] = d_w[(size_t)(bh * Vv + v) * 520 + chunk * 64 + ii];
    }
    __syncthreads();

    float acc[Vv] = {0.f, 0.f, 0.f, 0.f, 0.f};
    size_t base = (size_t)(b * Nn + chunk * 64) * HD + head * Dd + c;
    for (int ii = 0; ii < 64; ii++) {
        float hv = d_h[base + (size_t)ii * HD];
#pragma unroll
        for (int v = 0; v < Vv; v++) acc[v] += w_sh[v][ii] * hv;
    }
    if (chunk == 0) {
#pragma unroll
        for (int v = 0; v < Vv; v++) {
            int vt = BN + b * Vv + v;
            float hs = d_h[(size_t)vt * HD + head * Dd + c];
            acc[v] += d_w[(size_t)(bh * Vv + v) * 520 + 512] * hs;
        }
    }
#pragma unroll
    for (int v = 0; v < Vv; v++)
        d_vpart[(size_t)((chunk * 128 + bh) * Vv + v) * Dd + c] = acc[v];
}

// ---------------- gelu + layernorm helpers ----------------------------------
__device__ __forceinline__ float gelu_exact(float x) {
    return 0.5f * x * (1.f + erff(x * 0.70710678118654752f));
}
__device__ __forceinline__ float block_sum(float v, float* red) {
    int c = threadIdx.x;
    red[c] = v;
    __syncthreads();
    for (int s = 128; s > 0; s >>= 1) {
        if (c < s) red[c] += red[c + s];
        __syncthreads();
    }
    float r = red[0];
    __syncthreads();
    return r;
}

// head-mean + bias + gelu + layernorm1 -> bf16 split g1
__global__ void k_norm1(const float* __restrict__ gat_bias,
                        const float* __restrict__ g, const float* __restrict__ bta) {
    __shared__ float red[256];
    int t = blockIdx.x;
    int c = threadIdx.x;
    float s;
    if (t < BN) {
        const float* hp = d_h + (size_t)t * HD;
        s = 0.25f * (hp[c] + hp[Dd + c] + hp[2 * Dd + c] + hp[3 * Dd + c]);
    } else {
        int tv = t - BN;
        int b = tv / Vv, v = tv % Vv;
        int bh0 = b * 4;
        float a = 0.f;
#pragma unroll
        for (int head = 0; head < 4; head++)
#pragma unroll
            for (int chunk = 0; chunk < 8; chunk++)
                a += d_vpart[(size_t)((chunk * 128 + bh0 + head) * Vv + v) * Dd + c];
        s = 0.25f * a;
    }
    s += gat_bias[c];
    float ge = gelu_exact(s);
    float mean = block_sum(ge, red) * (1.f / Dd);
    float dlt = ge - mean;
    float var = block_sum(dlt * dlt, red) * (1.f / Dd);
    float val = dlt * rsqrtf(var + 1e-5f) * g[c] + bta[c];
    __nv_bfloat16 hi, lo;
    split_bf16(val, hi, lo);
    d_G1hi[(size_t)t * Dd + c] = hi;
    d_G1lo[(size_t)t * Dd + c] = lo;
}

// per-batch sum of virtual-node xw rows
__global__ void k_vsum() {
    int b = blockIdx.x;
    int c = threadIdx.x;
    float s = 0.f;
#pragma unroll
    for (int v = 0; v < Vv; v++)
        s += d_xw[(size_t)(BN + b * Vv + v) * Dd + c];
    d_S[b * Dd + c] = s;
}

// GCN combine + bias + gelu + layernorm2 -> out
__global__ void k_final(const float* __restrict__ gcn_bias,
                        const float* __restrict__ g, const float* __restrict__ bta,
                        float* __restrict__ out) {
    __shared__ float red[256];
    int t = blockIdx.x;
    int c = threadIdx.x;
    int b = t / Nn;
    const float inv_sqrt6 = 0.40824829046386301637f;
    const float inv6 = 0.16666666666666666667f;
    float u = inv_sqrt6 * d_S[b * Dd + c] + inv6 * d_xw[(size_t)t * Dd + c] + gcn_bias[c];
    float ge = gelu_exact(u);
    float mean = block_sum(ge, red) * (1.f / Dd);
    float dlt = ge - mean;
    float var = block_sum(dlt * dlt, red) * (1.f / Dd);
    out[(size_t)t * Dd + c] = dlt * rsqrtf(var + 1e-5f) * g[c] + bta[c];
}

// ---------------------------------------------------------------------------
extern "C" void kernel_launch(void* const* d_in, const int* in_sizes, int n_in,
                              void* d_out, int out_size) {
    const float* x        = (const float*)d_in[0];
    const float* vn       = (const float*)d_in[2];
    const float* gat_W    = (const float*)d_in[3];
    const float* att_src  = (const float*)d_in[4];
    const float* att_dst  = (const float*)d_in[5];
    const float* gat_bias = (const float*)d_in[6];
    const float* gcn_W    = (const float*)d_in[7];
    const float* gcn_bias = (const float*)d_in[8];
    const float* n1g      = (const float*)d_in[9];
    const float* n1b      = (const float*)d_in[10];
    const float* n2g      = (const float*)d_in[11];
    const float* n2b      = (const float*)d_in[12];
    float* out = (float*)d_out;

    __nv_bfloat16 *pAhi, *pAlo, *pB1hi, *pB1lo, *pB2hi, *pB2lo, *pG1hi, *pG1lo;
    float *pH, *pXW;
    cudaGetSymbolAddress((void**)&pAhi,  d_Ahi);
    cudaGetSymbolAddress((void**)&pAlo,  d_Alo);
    cudaGetSymbolAddress((void**)&pB1hi, d_B1hi);
    cudaGetSymbolAddress((void**)&pB1lo, d_B1lo);
    cudaGetSymbolAddress((void**)&pB2hi, d_B2hi);
    cudaGetSymbolAddress((void**)&pB2lo, d_B2lo);
    cudaGetSymbolAddress((void**)&pG1hi, d_G1hi);
    cudaGetSymbolAddress((void**)&pG1lo, d_G1lo);
    cudaGetSymbolAddress((void**)&pH,    d_h);
    cudaGetSymbolAddress((void**)&pXW,   d_xw);

    k_build_split<<<Tt, 256>>>(x, vn);
    k_cvt_bt<<<HD, 256>>>(gat_W, HD, pB1hi, pB1lo);
    k_cvt_bt<<<Dd, 256>>>(gcn_W, Dd, pB2hi, pB2lo);

    k_mma_gemm<<<dim3(HD / 128, TP / 128), 256>>>(pAhi, pAlo, pB1hi, pB1lo, pH, HD);

    k_att<<<Tt, 256>>>(att_src, att_dst);
    k_vw<<<128, 256>>>();
    k_vagg2<<<dim3(128, 8), 256>>>();
    k_norm1<<<Tt, 256>>>(gat_bias, n1g, n1b);

    k_mma_gemm<<<dim3(Dd / 128, TP / 128), 256>>>(pG1hi, pG1lo, pB2hi, pB2lo, pXW, Dd);

    k_vsum<<<Bb, 256>>>();
    k_final<<<BN, 256>>>(gcn_bias, n2g, n2b, out);
}

// round 4
// speedup vs baseline: 1.7042x; 1.1041x over previous
#include <cuda_runtime.h>
#include <cuda_bf16.h>
#include <math.h>
#include <stdint.h>

#define Bb 32
#define Nn 512
#define Vv 5
#define Dd 256
#define Hh 4
#define BN (Bb*Nn)            // 16384 real nodes
#define Tt (BN + Bb*Vv)       // 16544 total nodes
#define TP 16640              // padded to 130*128 rows
#define HD (Hh*Dd)            // 1024
#define Kk 256

// ---------------- scratch (static device memory; zero-initialized) ----------
__device__ __nv_bfloat16 d_Ahi[(size_t)TP*Kk];
__device__ __nv_bfloat16 d_Alo[(size_t)TP*Kk];
__device__ __nv_bfloat16 d_B1hi[HD*Kk];   // gat_W^T  [1024,256]
__device__ __nv_bfloat16 d_B1lo[HD*Kk];
__device__ __nv_bfloat16 d_B2hi[Dd*Kk];   // gcn_W^T  [256,256]
__device__ __nv_bfloat16 d_B2lo[Dd*Kk];
__device__ float d_h[(size_t)TP*HD];      // GAT pre-act [TP,1024] fp32
__device__ float d_asrc[Tt*Hh];
__device__ float d_adst[Tt*Hh];
__device__ float d_w[128*Vv*520];         // softmax weights [bh][v][513]
__device__ float d_vpart[8*128*Vv*Dd];    // chunked virtual aggregation partials
__device__ __nv_bfloat16 d_G1hi[(size_t)TP*Kk];
__device__ __nv_bfloat16 d_G1lo[(size_t)TP*Kk];
__device__ float d_xw[(size_t)TP*Dd];
__device__ float d_S[Bb*Dd];

// ---------------- helpers ----------------------------------------------
__device__ __forceinline__ uint32_t smem_u32(const void* p) {
    uint32_t a;
    asm("{ .reg .u64 t; cvta.to.shared.u64 t, %1; cvt.u32.u64 %0, t; }"
        : "=r"(a) : "l"(p));
    return a;
}
// 64B-row XOR swizzle: toggles byte bits [5:4] with row bits [2:1]
__device__ __forceinline__ uint32_t sw64(uint32_t off) { return off ^ ((off >> 3) & 0x30); }

__device__ __forceinline__ void ldmx4(uint32_t* r, uint32_t addr) {
    asm volatile("ldmatrix.sync.aligned.m8n8.x4.shared.b16 {%0,%1,%2,%3}, [%4];"
                 : "=r"(r[0]), "=r"(r[1]), "=r"(r[2]), "=r"(r[3]) : "r"(addr));
}
__device__ __forceinline__ void mma16816(float* d, const uint32_t* a, uint32_t b0, uint32_t b1) {
    asm volatile(
        "mma.sync.aligned.m16n8k16.row.col.f32.bf16.bf16.f32 "
        "{%0,%1,%2,%3}, {%4,%5,%6,%7}, {%8,%9}, {%0,%1,%2,%3};"
        : "+f"(d[0]), "+f"(d[1]), "+f"(d[2]), "+f"(d[3])
        : "r"(a[0]), "r"(a[1]), "r"(a[2]), "r"(a[3]), "r"(b0), "r"(b1));
}
__device__ __forceinline__ void cp16(uint32_t smem_addr, const void* gptr) {
    asm volatile("cp.async.cg.shared.global [%0], [%1], 16;"
                 :: "r"(smem_addr), "l"(gptr));
}
__device__ __forceinline__ void cp_commit() {
    asm volatile("cp.async.commit_group;" ::: "memory");
}
__device__ __forceinline__ void cp_wait1() {
    asm volatile("cp.async.wait_group 1;" ::: "memory");
}

__device__ __forceinline__ void split_bf16(float v, __nv_bfloat16& hi, __nv_bfloat16& lo) {
    hi = __float2bfloat16(v);
    lo = __float2bfloat16(v - __bfloat162float(hi));
}

// ---------------- split builders -----------------------------------------
__global__ void k_build_split(const float* __restrict__ x, const float* __restrict__ vn) {
    int idx = blockIdx.x * 256 + threadIdx.x;   // < Tt*Dd
    int t = idx >> 8;
    int c = idx & 255;
    float v = (t < BN) ? x[idx] : vn[((t - BN) % Vv) * Dd + c];
    __nv_bfloat16 hi, lo;
    split_bf16(v, hi, lo);
    d_Ahi[idx] = hi;
    d_Alo[idx] = lo;
}

// transpose + split:  B [K=256, N] fp32 -> Bt [N, 256] bf16 hi/lo
__global__ void k_cvt_bt(const float* __restrict__ B, int N,
                         __nv_bfloat16* __restrict__ Bthi, __nv_bfloat16* __restrict__ Btlo) {
    int idx = blockIdx.x * 256 + threadIdx.x;   // idx = n*256 + k
    int n = idx >> 8;
    int k = idx & 255;
    float v = B[k * N + n];
    __nv_bfloat16 hi, lo;
    split_bf16(v, hi, lo);
    Bthi[idx] = hi;
    Btlo[idx] = lo;
}

// ---------------- pipelined mma.sync split-bf16 GEMM -----------------------
// C[TP, Ncols] = A[TP,256] * Bt[Ncols,256]^T, fp32 out.
// grid (Ncols/128, TP/128), 256 threads (8 warps = 2m x 4n), warp 64x32.
// 3-stage cp.async ring buffer, 32KB/stage.
#define NSTAGE 3
#define STAGE_BYTES 32768
#define OFF_AH 0
#define OFF_AL 8192
#define OFF_BH 16384
#define OFF_BL 24576

__global__ void __launch_bounds__(256, 1) k_mma_gemm(
    const __nv_bfloat16* __restrict__ Ahi, const __nv_bfloat16* __restrict__ Alo,
    const __nv_bfloat16* __restrict__ Bhi, const __nv_bfloat16* __restrict__ Blo,
    float* __restrict__ C, int Ncols)
{
    extern __shared__ __align__(128) char smem[];
    const uint32_t sbase = smem_u32(smem);

    const int tid = threadIdx.x;
    const int wid = tid >> 5, lane = tid & 31;
    const int wm = (wid >> 2) * 64;     // warp m offset (0 or 64)
    const int wn = (wid & 3) * 32;      // warp n offset
    const int mBase = blockIdx.y * 128;
    const int nBase = blockIdx.x * 128;

    // per-thread load slots: 2 rows-of-4 slots (512 16B-copies per tile / 256 thr)
    const int lrow0 = tid >> 2;          // 0..63
    const int lc16  = tid & 3;
    // precompute source pointers (uint4 granularity; 32 uint4 per 256-bf16 row)
    const uint4* A4h = reinterpret_cast<const uint4*>(Ahi);
    const uint4* A4l = reinterpret_cast<const uint4*>(Alo);
    const uint4* B4h = reinterpret_cast<const uint4*>(Bhi);
    const uint4* B4l = reinterpret_cast<const uint4*>(Blo);

    float acc[4][4][4];
#pragma unroll
    for (int i = 0; i < 4; i++)
#pragma unroll
        for (int j = 0; j < 4; j++)
#pragma unroll
            for (int e = 0; e < 4; e++) acc[i][j][e] = 0.f;

    // ldmatrix lane address components
    const uint32_t aRow = (uint32_t)((lane & 7) + (lane & 8));
    const uint32_t aColB = (lane & 16) ? 16u : 0u;
    const uint32_t bRow = (uint32_t)((lane & 7) + ((lane & 16) >> 1));
    const uint32_t bColB = (lane & 8) ? 16u : 0u;

    // ---- prefetch helper (macro-ish lambda) ----
    auto prefetch = [&](int kc) {
        uint32_t st = sbase + (kc % NSTAGE) * STAGE_BYTES;
#pragma unroll
        for (int q = 0; q < 2; q++) {
            int row = lrow0 + q * 64;
            uint32_t sw = sw64((uint32_t)(row * 64 + lc16 * 16));
            int ga = (mBase + row) * 32 + kc * 4 + lc16;
            int gb = (nBase + row) * 32 + kc * 4 + lc16;
            cp16(st + OFF_AH + sw, A4h + ga);
            cp16(st + OFF_AL + sw, A4l + ga);
            cp16(st + OFF_BH + sw, B4h + gb);
            cp16(st + OFF_BL + sw, B4l + gb);
        }
    };

    // prologue: stages 0,1
    prefetch(0); cp_commit();
    prefetch(1); cp_commit();

    for (int kc = 0; kc < 8; kc++) {   // 8 chunks of K=32
        cp_wait1();                     // stage kc resident
        __syncthreads();                // all threads see it; prev compute done
        if (kc + 2 < 8) prefetch(kc + 2);
        cp_commit();                    // commit every iter (may be empty)

        uint32_t st = sbase + (kc % NSTAGE) * STAGE_BYTES;
#pragma unroll
        for (int s = 0; s < 2; s++) {
            uint32_t ah[4][4], al[4][4], bh[2][4], bl[2][4];
#pragma unroll
            for (int mt = 0; mt < 4; mt++) {
                uint32_t byteo = sw64((uint32_t)((wm + mt * 16 + aRow) * 64) + s * 32u + aColB);
                ldmx4(ah[mt], st + OFF_AH + byteo);
                ldmx4(al[mt], st + OFF_AL + byteo);
            }
#pragma unroll
            for (int ng = 0; ng < 2; ng++) {
                uint32_t byteo = sw64((uint32_t)((wn + ng * 16 + bRow) * 64) + s * 32u + bColB);
                ldmx4(bh[ng], st + OFF_BH + byteo);
                ldmx4(bl[ng], st + OFF_BL + byteo);
            }
#pragma unroll
            for (int mt = 0; mt < 4; mt++)
#pragma unroll
                for (int ng = 0; ng < 2; ng++) {
                    mma16816(acc[mt][ng * 2],     ah[mt], bh[ng][0], bh[ng][1]);
                    mma16816(acc[mt][ng * 2 + 1], ah[mt], bh[ng][2], bh[ng][3]);
                    mma16816(acc[mt][ng * 2],     ah[mt], bl[ng][0], bl[ng][1]);
                    mma16816(acc[mt][ng * 2 + 1], ah[mt], bl[ng][2], bl[ng][3]);
                    mma16816(acc[mt][ng * 2],     al[mt], bh[ng][0], bh[ng][1]);
                    mma16816(acc[mt][ng * 2 + 1], al[mt], bh[ng][2], bh[ng][3]);
                }
        }
        __syncthreads();                // done reading stage kc%NSTAGE
    }

    // ---- epilogue ----
    int mThr = mBase + wm + (lane >> 2);
    int nThr = nBase + wn + (lane & 3) * 2;
#pragma unroll
    for (int mt = 0; mt < 4; mt++)
#pragma unroll
        for (int nt = 0; nt < 4; nt++) {
            int r0 = mThr + mt * 16;
            int cc = nThr + nt * 8;
            float2 v0 = make_float2(acc[mt][nt][0], acc[mt][nt][1]);
            float2 v1 = make_float2(acc[mt][nt][2], acc[mt][nt][3]);
            *reinterpret_cast<float2*>(C + (size_t)r0 * Ncols + cc) = v0;
            *reinterpret_cast<float2*>(C + (size_t)(r0 + 8) * Ncols + cc) = v1;
        }
}

// ---------------- attention scores ------------------------------------------
__global__ void k_att(const float* __restrict__ att_src, const float* __restrict__ att_dst) {
    int t = blockIdx.x;
    int w = threadIdx.x >> 5;
    int lane = threadIdx.x & 31;
    int head = w >> 1;
    bool is_dst = (w & 1);
    const float* hp = d_h + (size_t)t * HD + head * Dd;
    const float* ap = (is_dst ? att_dst : att_src) + head * Dd;
    float s = 0.f;
#pragma unroll
    for (int j = 0; j < 8; j++) s += hp[lane + 32 * j] * ap[lane + 32 * j];
#pragma unroll
    for (int o = 16; o; o >>= 1) s += __shfl_xor_sync(0xffffffffu, s, o);
    if (lane == 0) {
        if (is_dst) d_adst[t * Hh + head] = s;
        else        d_asrc[t * Hh + head] = s;
    }
}

__device__ __forceinline__ float lrelu(float x) { return x > 0.f ? x : 0.2f * x; }

// ---------------- softmax weights (per batch,head) --------------------------
__global__ void k_vw() {
    int bh = blockIdx.x;               // 0..127
    int b = bh >> 2, head = bh & 3;
    int tid = threadIdx.x;

    __shared__ float asrc_sh[Nn];
    __shared__ float e_sh[Nn];
    __shared__ float red[256];

    for (int i = tid; i < Nn; i += 256)
        asrc_sh[i] = d_asrc[(b * Nn + i) * Hh + head];
    __syncthreads();

    for (int v = 0; v < Vv; v++) {
        int vt = BN + b * Vv + v;
        float adst = d_adst[vt * Hh + head];
        float aself = lrelu(d_asrc[vt * Hh + head] + adst);

        float lm = aself;
        for (int i = tid; i < Nn; i += 256) lm = fmaxf(lm, lrelu(asrc_sh[i] + adst));
        red[tid] = lm;
        __syncthreads();
        for (int s = 128; s > 0; s >>= 1) {
            if (tid < s) red[tid] = fmaxf(red[tid], red[tid + s]);
            __syncthreads();
        }
        float m = red[0];
        __syncthreads();

        float ls = 0.f;
        for (int i = tid; i < Nn; i += 256) {
            float e = expf(lrelu(asrc_sh[i] + adst) - m);
            e_sh[i] = e;
            ls += e;
        }
        float eS = expf(aself - m);
        if (tid == 0) ls += eS;
        red[tid] = ls;
        __syncthreads();
        for (int s = 128; s > 0; s >>= 1) {
            if (tid < s) red[tid] += red[tid + s];
            __syncthreads();
        }
        float inv = 1.f / red[0];
        __syncthreads();

        float* wp = d_w + (size_t)(bh * Vv + v) * 520;
        for (int i = tid; i < Nn; i += 256) wp[i] = e_sh[i] * inv;
        if (tid == 0) wp[512] = eS * inv;
        __syncthreads();
    }
}

// ---------------- chunked virtual aggregation -------------------------------
// grid (128, 8): (batch*head, i-chunk of 64). block 256 = channel.
__global__ void k_vagg2() {
    int bh = blockIdx.x;
    int chunk = blockIdx.y;
    int b = bh >> 2, head = bh & 3;
    int c = threadIdx.x;

    __shared__ float w_sh[Vv][64];
    for (int idx = c; idx < Vv * 64; idx += 256) {
        int v = idx >> 6, ii = idx & 63;
        w_sh[v][ii] = d_w[(size_t)(bh * Vv + v) * 520 + chunk * 64 + ii];
    }
    __syncthreads();

    float acc[Vv] = {0.f, 0.f, 0.f, 0.f, 0.f};
    size_t base = (size_t)(b * Nn + chunk * 64) * HD + head * Dd + c;
    for (int ii = 0; ii < 64; ii++) {
        float hv = d_h[base + (size_t)ii * HD];
#pragma unroll
        for (int v = 0; v < Vv; v++) acc[v] += w_sh[v][ii] * hv;
    }
    if (chunk == 0) {
#pragma unroll
        for (int v = 0; v < Vv; v++) {
            int vt = BN + b * Vv + v;
            float hs = d_h[(size_t)vt * HD + head * Dd + c];
            acc[v] += d_w[(size_t)(bh * Vv + v) * 520 + 512] * hs;
        }
    }
#pragma unroll
    for (int v = 0; v < Vv; v++)
        d_vpart[(size_t)((chunk * 128 + bh) * Vv + v) * Dd + c] = acc[v];
}

// ---------------- gelu + layernorm helpers ----------------------------------
__device__ __forceinline__ float gelu_exact(float x) {
    return 0.5f * x * (1.f + erff(x * 0.70710678118654752f));
}
__device__ __forceinline__ float block_sum(float v, float* red) {
    int c = threadIdx.x;
    red[c] = v;
    __syncthreads();
    for (int s = 128; s > 0; s >>= 1) {
        if (c < s) red[c] += red[c + s];
        __syncthreads();
    }
    float r = red[0];
    __syncthreads();
    return r;
}

// head-mean + bias + gelu + layernorm1 -> bf16 split g1
__global__ void k_norm1(const float* __restrict__ gat_bias,
                        const float* __restrict__ g, const float* __restrict__ bta) {
    __shared__ float red[256];
    int t = blockIdx.x;
    int c = threadIdx.x;
    float s;
    if (t < BN) {
        const float* hp = d_h + (size_t)t * HD;
        s = 0.25f * (hp[c] + hp[Dd + c] + hp[2 * Dd + c] + hp[3 * Dd + c]);
    } else {
        int tv = t - BN;
        int b = tv / Vv, v = tv % Vv;
        int bh0 = b * 4;
        float a = 0.f;
#pragma unroll
        for (int head = 0; head < 4; head++)
#pragma unroll
            for (int chunk = 0; chunk < 8; chunk++)
                a += d_vpart[(size_t)((chunk * 128 + bh0 + head) * Vv + v) * Dd + c];
        s = 0.25f * a;
    }
    s += gat_bias[c];
    float ge = gelu_exact(s);
    float mean = block_sum(ge, red) * (1.f / Dd);
    float dlt = ge - mean;
    float var = block_sum(dlt * dlt, red) * (1.f / Dd);
    float val = dlt * rsqrtf(var + 1e-5f) * g[c] + bta[c];
    __nv_bfloat16 hi, lo;
    split_bf16(val, hi, lo);
    d_G1hi[(size_t)t * Dd + c] = hi;
    d_G1lo[(size_t)t * Dd + c] = lo;
}

// per-batch sum of virtual-node xw rows
__global__ void k_vsum() {
    int b = blockIdx.x;
    int c = threadIdx.x;
    float s = 0.f;
#pragma unroll
    for (int v = 0; v < Vv; v++)
        s += d_xw[(size_t)(BN + b * Vv + v) * Dd + c];
    d_S[b * Dd + c] = s;
}

// GCN combine + bias + gelu + layernorm2 -> out
__global__ void k_final(const float* __restrict__ gcn_bias,
                        const float* __restrict__ g, const float* __restrict__ bta,
                        float* __restrict__ out) {
    __shared__ float red[256];
    int t = blockIdx.x;
    int c = threadIdx.x;
    int b = t / Nn;
    const float inv_sqrt6 = 0.40824829046386301637f;
    const float inv6 = 0.16666666666666666667f;
    float u = inv_sqrt6 * d_S[b * Dd + c] + inv6 * d_xw[(size_t)t * Dd + c] + gcn_bias[c];
    float ge = gelu_exact(u);
    float mean = block_sum(ge, red) * (1.f / Dd);
    float dlt = ge - mean;
    float var = block_sum(dlt * dlt, red) * (1.f / Dd);
    out[(size_t)t * Dd + c] = dlt * rsqrtf(var + 1e-5f) * g[c] + bta[c];
}

// ---------------------------------------------------------------------------
extern "C" void kernel_launch(void* const* d_in, const int* in_sizes, int n_in,
                              void* d_out, int out_size) {
    const float* x        = (const float*)d_in[0];
    const float* vn       = (const float*)d_in[2];
    const float* gat_W    = (const float*)d_in[3];
    const float* att_src  = (const float*)d_in[4];
    const float* att_dst  = (const float*)d_in[5];
    const float* gat_bias = (const float*)d_in[6];
    const float* gcn_W    = (const float*)d_in[7];
    const float* gcn_bias = (const float*)d_in[8];
    const float* n1g      = (const float*)d_in[9];
    const float* n1b      = (const float*)d_in[10];
    const float* n2g      = (const float*)d_in[11];
    const float* n2b      = (const float*)d_in[12];
    float* out = (float*)d_out;

    const int SMEM_BYTES = NSTAGE * STAGE_BYTES;   // 96 KB
    cudaFuncSetAttribute(k_mma_gemm, cudaFuncAttributeMaxDynamicSharedMemorySize, SMEM_BYTES);

    __nv_bfloat16 *pAhi, *pAlo, *pB1hi, *pB1lo, *pB2hi, *pB2lo, *pG1hi, *pG1lo;
    float *pH, *pXW;
    cudaGetSymbolAddress((void**)&pAhi,  d_Ahi);
    cudaGetSymbolAddress((void**)&pAlo,  d_Alo);
    cudaGetSymbolAddress((void**)&pB1hi, d_B1hi);
    cudaGetSymbolAddress((void**)&pB1lo, d_B1lo);
    cudaGetSymbolAddress((void**)&pB2hi, d_B2hi);
    cudaGetSymbolAddress((void**)&pB2lo, d_B2lo);
    cudaGetSymbolAddress((void**)&pG1hi, d_G1hi);
    cudaGetSymbolAddress((void**)&pG1lo, d_G1lo);
    cudaGetSymbolAddress((void**)&pH,    d_h);
    cudaGetSymbolAddress((void**)&pXW,   d_xw);

    k_build_split<<<Tt, 256>>>(x, vn);
    k_cvt_bt<<<HD, 256>>>(gat_W, HD, pB1hi, pB1lo);
    k_cvt_bt<<<Dd, 256>>>(gcn_W, Dd, pB2hi, pB2lo);

    k_mma_gemm<<<dim3(HD / 128, TP / 128), 256, SMEM_BYTES>>>(pAhi, pAlo, pB1hi, pB1lo, pH, HD);

    k_att<<<Tt, 256>>>(att_src, att_dst);
    k_vw<<<128, 256>>>();
    k_vagg2<<<dim3(128, 8), 256>>>();
    k_norm1<<<Tt, 256>>>(gat_bias, n1g, n1b);

    k_mma_gemm<<<dim3(Dd / 128, TP / 128), 256, SMEM_BYTES>>>(pG1hi, pG1lo, pB2hi, pB2lo, pXW, Dd);

    k_vsum<<<Bb, 256>>>();
    k_final<<<BN, 256>>>(gcn_bias, n2g, n2b, out);
}

// round 5
// speedup vs baseline: 1.8029x; 1.0579x over previous
#include <cuda_runtime.h>
#include <cuda_bf16.h>
#include <math.h>
#include <stdint.h>

#define Bb 32
#define Nn 512
#define Vv 5
#define Dd 256
#define Hh 4
#define BN (Bb*Nn)            // 16384 real nodes
#define Tt (BN + Bb*Vv)       // 16544 total nodes
#define TP 16640              // padded to 130*128 rows
#define Kk 256

// ---------------- scratch (static device memory; zero-initialized) ----------
__device__ float d_allf[(size_t)Tt*Dd];        // all_nodes fp32
__device__ __nv_bfloat16 d_Ahi[(size_t)TP*Kk];
__device__ __nv_bfloat16 d_Alo[(size_t)TP*Kk];
__device__ __nv_bfloat16 d_WmHi[Dd*Kk];        // head-mean of gat_W, transposed [n][k]
__device__ __nv_bfloat16 d_WmLo[Dd*Kk];
__device__ __nv_bfloat16 d_B2hi[Dd*Kk];        // gcn_W^T
__device__ __nv_bfloat16 d_B2lo[Dd*Kk];
__device__ float d_wsrc[Kk*Hh];                // gat_W @ att_src per head  [k][h]
__device__ float d_wdst[Kk*Hh];
__device__ float d_hmean[(size_t)TP*Dd];       // all_nodes @ Wm
__device__ float d_asrc[Tt*Hh];
__device__ float d_adst[Tt*Hh];
__device__ float d_w[128*Vv*520];              // softmax weights [bh][v][513]
__device__ float d_ypart[8*Bb*20*Dd];          // chunked weighted-x partials
__device__ float d_Y[Bb*Vv*Hh*Dd];             // y' [bv][h*256+k]
__device__ float d_gvirt[Bb*Vv*Dd];            // virtual gat_out (head mean)
__device__ __nv_bfloat16 d_G1hi[(size_t)TP*Kk];
__device__ __nv_bfloat16 d_G1lo[(size_t)TP*Kk];
__device__ float d_xw[(size_t)TP*Dd];
__device__ float d_S[Bb*Dd];

// ---------------- helpers ----------------------------------------------
__device__ __forceinline__ uint32_t smem_u32(const void* p) {
    uint32_t a;
    asm("{ .reg .u64 t; cvta.to.shared.u64 t, %1; cvt.u32.u64 %0, t; }"
        : "=r"(a) : "l"(p));
    return a;
}
__device__ __forceinline__ uint32_t sw64(uint32_t off) { return off ^ ((off >> 3) & 0x30); }

__device__ __forceinline__ void ldmx4(uint32_t* r, uint32_t addr) {
    asm volatile("ldmatrix.sync.aligned.m8n8.x4.shared.b16 {%0,%1,%2,%3}, [%4];"
                 : "=r"(r[0]), "=r"(r[1]), "=r"(r[2]), "=r"(r[3]) : "r"(addr));
}
__device__ __forceinline__ void mma16816(float* d, const uint32_t* a, uint32_t b0, uint32_t b1) {
    asm volatile(
        "mma.sync.aligned.m16n8k16.row.col.f32.bf16.bf16.f32 "
        "{%0,%1,%2,%3}, {%4,%5,%6,%7}, {%8,%9}, {%0,%1,%2,%3};"
        : "+f"(d[0]), "+f"(d[1]), "+f"(d[2]), "+f"(d[3])
        : "r"(a[0]), "r"(a[1]), "r"(a[2]), "r"(a[3]), "r"(b0), "r"(b1));
}
__device__ __forceinline__ void cp16(uint32_t smem_addr, const void* gptr) {
    asm volatile("cp.async.cg.shared.global [%0], [%1], 16;"
                 :: "r"(smem_addr), "l"(gptr));
}
__device__ __forceinline__ void cp_commit() {
    asm volatile("cp.async.commit_group;" ::: "memory");
}
__device__ __forceinline__ void cp_wait1() {
    asm volatile("cp.async.wait_group 1;" ::: "memory");
}
__device__ __forceinline__ void split_bf16(float v, __nv_bfloat16& hi, __nv_bfloat16& lo) {
    hi = __float2bfloat16(v);
    lo = __float2bfloat16(v - __bfloat162float(hi));
}

// ---------------- builders -----------------------------------------
// all_nodes (fp32 + bf16 split)
__global__ void k_build(const float* __restrict__ x, const float* __restrict__ vn) {
    int idx = blockIdx.x * 256 + threadIdx.x;   // < Tt*Dd
    int t = idx >> 8;
    int c = idx & 255;
    float v = (t < BN) ? x[idx] : vn[((t - BN) % Vv) * Dd + c];
    d_allf[idx] = v;
    __nv_bfloat16 hi, lo;
    split_bf16(v, hi, lo);
    d_Ahi[idx] = hi;
    d_Alo[idx] = lo;
}

// wsrc[k][h] = <gat_W[k, h*256: ], att_src[h]>, same for dst. 2048 warps.
__global__ void k_watt(const float* __restrict__ gat_W,
                       const float* __restrict__ att_src, const float* __restrict__ att_dst) {
    int gw = blockIdx.x * 8 + (threadIdx.x >> 5);   // 0..2047
    int lane = threadIdx.x & 31;
    int k = gw >> 3;
    int h = (gw >> 1) & 3;
    bool is_dst = gw & 1;
    const float* wp = gat_W + (size_t)k * 1024 + h * 256;
    const float* ap = (is_dst ? att_dst : att_src) + h * 256;
    float s = 0.f;
#pragma unroll
    for (int j = 0; j < 8; j++) s += wp[lane + 32 * j] * ap[lane + 32 * j];
#pragma unroll
    for (int o = 16; o; o >>= 1) s += __shfl_xor_sync(0xffffffffu, s, o);
    if (lane == 0) {
        if (is_dst) d_wdst[k * 4 + h] = s;
        else        d_wsrc[k * 4 + h] = s;
    }
}

// Wm^T[n][k] = 0.25 * sum_h gat_W[k, h*256+n], split bf16
__global__ void k_wm(const float* __restrict__ gat_W) {
    int n = blockIdx.x;
    int k = threadIdx.x;
    const float* p = gat_W + (size_t)k * 1024 + n;
    float v = 0.25f * (p[0] + p[256] + p[512] + p[768]);
    __nv_bfloat16 hi, lo;
    split_bf16(v, hi, lo);
    d_WmHi[n * 256 + k] = hi;
    d_WmLo[n * 256 + k] = lo;
}

// transpose + split: gcn_W [256,256] -> Bt [n][k]
__global__ void k_cvt_bt(const float* __restrict__ B) {
    int idx = blockIdx.x * 256 + threadIdx.x;
    int n = idx >> 8;
    int k = idx & 255;
    float v = B[k * 256 + n];
    __nv_bfloat16 hi, lo;
    split_bf16(v, hi, lo);
    d_B2hi[idx] = hi;
    d_B2lo[idx] = lo;
}

// ---------------- pipelined mma.sync split-bf16 GEMM -----------------------
// C[TP, 256] = A[TP,256] * Bt[256,256]^T. grid (2, 130), 256 thr, 2 CTA/SM.
#define NSTAGE 2
#define STAGE_BYTES 32768
#define OFF_AH 0
#define OFF_AL 8192
#define OFF_BH 16384
#define OFF_BL 24576

__global__ void __launch_bounds__(256, 2) k_mma_gemm(
    const __nv_bfloat16* __restrict__ Ahi, const __nv_bfloat16* __restrict__ Alo,
    const __nv_bfloat16* __restrict__ Bhi, const __nv_bfloat16* __restrict__ Blo,
    float* __restrict__ C)
{
    extern __shared__ __align__(128) char smem[];
    const uint32_t sbase = smem_u32(smem);

    const int tid = threadIdx.x;
    const int wid = tid >> 5, lane = tid & 31;
    const int wm = (wid >> 2) * 64;
    const int wn = (wid & 3) * 32;
    const int mBase = blockIdx.y * 128;
    const int nBase = blockIdx.x * 128;

    const int lrow0 = tid >> 2;
    const int lc16  = tid & 3;
    const uint4* A4h = reinterpret_cast<const uint4*>(Ahi);
    const uint4* A4l = reinterpret_cast<const uint4*>(Alo);
    const uint4* B4h = reinterpret_cast<const uint4*>(Bhi);
    const uint4* B4l = reinterpret_cast<const uint4*>(Blo);

    float acc[4][4][4];
#pragma unroll
    for (int i = 0; i < 4; i++)
#pragma unroll
        for (int j = 0; j < 4; j++)
#pragma unroll
            for (int e = 0; e < 4; e++) acc[i][j][e] = 0.f;

    const uint32_t aRow = (uint32_t)((lane & 7) + (lane & 8));
    const uint32_t aColB = (lane & 16) ? 16u : 0u;
    const uint32_t bRow = (uint32_t)((lane & 7) + ((lane & 16) >> 1));
    const uint32_t bColB = (lane & 8) ? 16u : 0u;

    auto prefetch = [&](int kc) {
        uint32_t st = sbase + (kc & 1) * STAGE_BYTES;
#pragma unroll
        for (int q = 0; q < 2; q++) {
            int row = lrow0 + q * 64;
            uint32_t sw = sw64((uint32_t)(row * 64 + lc16 * 16));
            int ga = (mBase + row) * 32 + kc * 4 + lc16;
            int gb = (nBase + row) * 32 + kc * 4 + lc16;
            cp16(st + OFF_AH + sw, A4h + ga);
            cp16(st + OFF_AL + sw, A4l + ga);
            cp16(st + OFF_BH + sw, B4h + gb);
            cp16(st + OFF_BL + sw, B4l + gb);
        }
    };

    prefetch(0); cp_commit();

    for (int kc = 0; kc < 8; kc++) {
        if (kc + 1 < 8) prefetch(kc + 1);
        cp_commit();
        cp_wait1();                 // stage kc resident
        __syncthreads();

        uint32_t st = sbase + (kc & 1) * STAGE_BYTES;
#pragma unroll
        for (int s = 0; s < 2; s++) {
            uint32_t bh[2][4], bl[2][4];
#pragma unroll
            for (int ng = 0; ng < 2; ng++) {
                uint32_t byteo = sw64((uint32_t)((wn + ng * 16 + bRow) * 64) + s * 32u + bColB);
                ldmx4(bh[ng], st + OFF_BH + byteo);
                ldmx4(bl[ng], st + OFF_BL + byteo);
            }
#pragma unroll
            for (int mt = 0; mt < 4; mt++) {
                uint32_t ah[4], al[4];
                uint32_t byteo = sw64((uint32_t)((wm + mt * 16 + aRow) * 64) + s * 32u + aColB);
                ldmx4(ah, st + OFF_AH + byteo);
                ldmx4(al, st + OFF_AL + byteo);
#pragma unroll
                for (int ng = 0; ng < 2; ng++) {
                    mma16816(acc[mt][ng * 2],     ah, bh[ng][0], bh[ng][1]);
                    mma16816(acc[mt][ng * 2 + 1], ah, bh[ng][2], bh[ng][3]);
                    mma16816(acc[mt][ng * 2],     ah, bl[ng][0], bl[ng][1]);
                    mma16816(acc[mt][ng * 2 + 1], ah, bl[ng][2], bl[ng][3]);
                    mma16816(acc[mt][ng * 2],     al, bh[ng][0], bh[ng][1]);
                    mma16816(acc[mt][ng * 2 + 1], al, bh[ng][2], bh[ng][3]);
                }
            }
        }
        __syncthreads();
    }

    int mThr = mBase + wm + (lane >> 2);
    int nThr = nBase + wn + (lane & 3) * 2;
#pragma unroll
    for (int mt = 0; mt < 4; mt++)
#pragma unroll
        for (int nt = 0; nt < 4; nt++) {
            int r0 = mThr + mt * 16;
            int cc = nThr + nt * 8;
            float2 v0 = make_float2(acc[mt][nt][0], acc[mt][nt][1]);
            float2 v1 = make_float2(acc[mt][nt][2], acc[mt][nt][3]);
            *reinterpret_cast<float2*>(C + (size_t)r0 * 256 + cc) = v0;
            *reinterpret_cast<float2*>(C + (size_t)(r0 + 8) * 256 + cc) = v1;
        }
}

// ---------------- attention scores from tiny projections --------------------
__global__ void k_scores() {
    int t = blockIdx.x;
    int w = threadIdx.x >> 5;
    int lane = threadIdx.x & 31;
    int head = w >> 1;
    bool is_dst = (w & 1);
    const float* xp = d_allf + (size_t)t * Dd;
    const float* wp = (is_dst ? d_wdst : d_wsrc);
    float s = 0.f;
#pragma unroll
    for (int j = 0; j < 8; j++) {
        int k = lane + 32 * j;
        s += xp[k] * wp[k * 4 + head];
    }
#pragma unroll
    for (int o = 16; o; o >>= 1) s += __shfl_xor_sync(0xffffffffu, s, o);
    if (lane == 0) {
        if (is_dst) d_adst[t * Hh + head] = s;
        else        d_asrc[t * Hh + head] = s;
    }
}

__device__ __forceinline__ float lrelu(float x) { return x > 0.f ? x : 0.2f * x; }

// ---------------- softmax weights (per batch,head) --------------------------
__global__ void k_vw() {
    int bh = blockIdx.x;               // 0..127
    int b = bh >> 2, head = bh & 3;
    int tid = threadIdx.x;

    __shared__ float asrc_sh[Nn];
    __shared__ float e_sh[Nn];
    __shared__ float red[256];

    for (int i = tid; i < Nn; i += 256)
        asrc_sh[i] = d_asrc[(b * Nn + i) * Hh + head];
    __syncthreads();

    for (int v = 0; v < Vv; v++) {
        int vt = BN + b * Vv + v;
        float adst = d_adst[vt * Hh + head];
        float aself = lrelu(d_asrc[vt * Hh + head] + adst);

        float lm = aself;
        for (int i = tid; i < Nn; i += 256) lm = fmaxf(lm, lrelu(asrc_sh[i] + adst));
        red[tid] = lm;
        __syncthreads();
        for (int s = 128; s > 0; s >>= 1) {
            if (tid < s) red[tid] = fmaxf(red[tid], red[tid + s]);
            __syncthreads();
        }
        float m = red[0];
        __syncthreads();

        float ls = 0.f;
        for (int i = tid; i < Nn; i += 256) {
            float e = expf(lrelu(asrc_sh[i] + adst) - m);
            e_sh[i] = e;
            ls += e;
        }
        float eS = expf(aself - m);
        if (tid == 0) ls += eS;
        red[tid] = ls;
        __syncthreads();
        for (int s = 128; s > 0; s >>= 1) {
            if (tid < s) red[tid] += red[tid + s];
            __syncthreads();
        }
        float inv = 1.f / red[0];
        __syncthreads();

        float* wp = d_w + (size_t)(bh * Vv + v) * 520;
        for (int i = tid; i < Nn; i += 256) wp[i] = e_sh[i] * inv;
        if (tid == 0) wp[512] = eS * inv;
        __syncthreads();
    }
}

// ---------------- weighted-x aggregation (chunked) --------------------------
// grid (32, 8): (batch, i-chunk of 64). block 256 = channel k.
// acc[vh] over 20 (v,h) combos; partials to d_ypart.
__global__ void k_yagg() {
    int b = blockIdx.x;
    int chunk = blockIdx.y;
    int c = threadIdx.x;

    __shared__ float w_sh[20][64];
    for (int idx = c; idx < 20 * 64; idx += 256) {
        int vh = idx >> 6, ii = idx & 63;
        int v = vh >> 2, h = vh & 3;
        w_sh[vh][ii] = d_w[(size_t)((b * 4 + h) * Vv + v) * 520 + chunk * 64 + ii];
    }
    __syncthreads();

    float acc[20];
#pragma unroll
    for (int j = 0; j < 20; j++) acc[j] = 0.f;

    size_t base = (size_t)(b * Nn + chunk * 64) * Dd + c;
    for (int ii = 0; ii < 64; ii++) {
        float xv = d_allf[base + (size_t)ii * Dd];
#pragma unroll
        for (int j = 0; j < 20; j++) acc[j] += w_sh[j][ii] * xv;
    }
#pragma unroll
    for (int j = 0; j < 20; j++)
        d_ypart[(size_t)((chunk * Bb + b) * 20 + j) * Dd + c] = acc[j];
}

// Y'[bv][h*256+k] = sum_chunks ypart + w_self * vn[v][k].  grid 640 (b,v,h).
__global__ void k_yfin(const float* __restrict__ vn) {
    int g = blockIdx.x;              // b*20 + v*4 + h
    int b = g / 20;
    int vh = g % 20;
    int v = vh >> 2, h = vh & 3;
    int k = threadIdx.x;
    float s = 0.f;
#pragma unroll
    for (int chunk = 0; chunk < 8; chunk++)
        s += d_ypart[(size_t)((chunk * Bb + b) * 20 + vh) * Dd + k];
    float wself = d_w[(size_t)((b * 4 + h) * Vv + v) * 520 + 512];
    s += wself * vn[v * Dd + k];
    d_Y[(size_t)((b * Vv + v) * Hh + h) * Dd + k] = s;
}

// gvirt[bv][c] = 0.25 * sum_j Y[bv][j] * gat_W[(j&255), (j>>8)*256 + c]
__global__ void k_vgemm(const float* __restrict__ gat_W) {
    int bv = blockIdx.x;             // 0..159
    int c = threadIdx.x;
    __shared__ float yrow[1024];
    for (int j = c; j < 1024; j += 256)
        yrow[j] = d_Y[(size_t)bv * 1024 + j];
    __syncthreads();
    float acc = 0.f;
    for (int j = 0; j < 1024; j++) {
        int k = j & 255, h = j >> 8;
        acc += yrow[j] * gat_W[(size_t)k * 1024 + h * 256 + c];
    }
    d_gvirt[(size_t)bv * Dd + c] = 0.25f * acc;
}

// ---------------- gelu + layernorm ----------------------------------
__device__ __forceinline__ float gelu_exact(float x) {
    return 0.5f * x * (1.f + erff(x * 0.70710678118654752f));
}
__device__ __forceinline__ float block_sum(float v, float* red) {
    int c = threadIdx.x;
    red[c] = v;
    __syncthreads();
    for (int s = 128; s > 0; s >>= 1) {
        if (c < s) red[c] += red[c + s];
        __syncthreads();
    }
    float r = red[0];
    __syncthreads();
    return r;
}

__global__ void k_norm1(const float* __restrict__ gat_bias,
                        const float* __restrict__ g, const float* __restrict__ bta) {
    __shared__ float red[256];
    int t = blockIdx.x;
    int c = threadIdx.x;
    float s = (t < BN) ? d_hmean[(size_t)t * Dd + c]
                       : d_gvirt[(size_t)(t - BN) * Dd + c];
    s += gat_bias[c];
    float ge = gelu_exact(s);
    float mean = block_sum(ge, red) * (1.f / Dd);
    float dlt = ge - mean;
    float var = block_sum(dlt * dlt, red) * (1.f / Dd);
    float val = dlt * rsqrtf(var + 1e-5f) * g[c] + bta[c];
    __nv_bfloat16 hi, lo;
    split_bf16(val, hi, lo);
    d_G1hi[(size_t)t * Dd + c] = hi;
    d_G1lo[(size_t)t * Dd + c] = lo;
}

__global__ void k_vsum() {
    int b = blockIdx.x;
    int c = threadIdx.x;
    float s = 0.f;
#pragma unroll
    for (int v = 0; v < Vv; v++)
        s += d_xw[(size_t)(BN + b * Vv + v) * Dd + c];
    d_S[b * Dd + c] = s;
}

__global__ void k_final(const float* __restrict__ gcn_bias,
                        const float* __restrict__ g, const float* __restrict__ bta,
                        float* __restrict__ out) {
    __shared__ float red[256];
    int t = blockIdx.x;
    int c = threadIdx.x;
    int b = t / Nn;
    const float inv_sqrt6 = 0.40824829046386301637f;
    const float inv6 = 0.16666666666666666667f;
    float u = inv_sqrt6 * d_S[b * Dd + c] + inv6 * d_xw[(size_t)t * Dd + c] + gcn_bias[c];
    float ge = gelu_exact(u);
    float mean = block_sum(ge, red) * (1.f / Dd);
    float dlt = ge - mean;
    float var = block_sum(dlt * dlt, red) * (1.f / Dd);
    out[(size_t)t * Dd + c] = dlt * rsqrtf(var + 1e-5f) * g[c] + bta[c];
}

// ---------------------------------------------------------------------------
extern "C" void kernel_launch(void* const* d_in, const int* in_sizes, int n_in,
                              void* d_out, int out_size) {
    const float* x        = (const float*)d_in[0];
    const float* vn       = (const float*)d_in[2];
    const float* gat_W    = (const float*)d_in[3];
    const float* att_src  = (const float*)d_in[4];
    const float* att_dst  = (const float*)d_in[5];
    const float* gat_bias = (const float*)d_in[6];
    const float* gcn_W    = (const float*)d_in[7];
    const float* gcn_bias = (const float*)d_in[8];
    const float* n1g      = (const float*)d_in[9];
    const float* n1b      = (const float*)d_in[10];
    const float* n2g      = (const float*)d_in[11];
    const float* n2b      = (const float*)d_in[12];
    float* out = (float*)d_out;

    const int SMEM_BYTES = NSTAGE * STAGE_BYTES;   // 64 KB
    cudaFuncSetAttribute(k_mma_gemm, cudaFuncAttributeMaxDynamicSharedMemorySize, SMEM_BYTES);

    __nv_bfloat16 *pAhi, *pAlo, *pWmHi, *pWmLo, *pB2hi, *pB2lo, *pG1hi, *pG1lo;
    float *pHM, *pXW;
    cudaGetSymbolAddress((void**)&pAhi,  d_Ahi);
    cudaGetSymbolAddress((void**)&pAlo,  d_Alo);
    cudaGetSymbolAddress((void**)&pWmHi, d_WmHi);
    cudaGetSymbolAddress((void**)&pWmLo, d_WmLo);
    cudaGetSymbolAddress((void**)&pB2hi, d_B2hi);
    cudaGetSymbolAddress((void**)&pB2lo, d_B2lo);
    cudaGetSymbolAddress((void**)&pG1hi, d_G1hi);
    cudaGetSymbolAddress((void**)&pG1lo, d_G1lo);
    cudaGetSymbolAddress((void**)&pHM,   d_hmean);
    cudaGetSymbolAddress((void**)&pXW,   d_xw);

    k_build<<<Tt, 256>>>(x, vn);
    k_watt<<<256, 256>>>(gat_W, att_src, att_dst);
    k_wm<<<256, 256>>>(gat_W);
    k_cvt_bt<<<256, 256>>>(gcn_W);

    k_mma_gemm<<<dim3(2, TP / 128), 256, SMEM_BYTES>>>(pAhi, pAlo, pWmHi, pWmLo, pHM);

    k_scores<<<Tt, 256>>>();
    k_vw<<<128, 256>>>();
    k_yagg<<<dim3(Bb, 8), 256>>>();
    k_yfin<<<Bb * 20, 256>>>(vn);
    k_vgemm<<<Bb * Vv, 256>>>(gat_W);
    k_norm1<<<Tt, 256>>>(gat_bias, n1g, n1b);

    k_mma_gemm<<<dim3(2, TP / 128), 256, SMEM_BYTES>>>(pG1hi, pG1lo, pB2hi, pB2lo, pXW);

    k_vsum<<<Bb, 256>>>();
    k_final<<<BN, 256>>>(gcn_bias, n2g, n2b, out);
}

// round 6
// speedup vs baseline: 2.1735x; 1.2055x over previous
#include <cuda_runtime.h>
#include <cuda_bf16.h>
#include <math.h>
#include <stdint.h>

#define Bb 32
#define Nn 512
#define Vv 5
#define Dd 256
#define Hh 4
#define BN (Bb*Nn)            // 16384 real nodes
#define Tt (BN + Bb*Vv)       // 16544 total nodes
#define TP 16640              // padded to 130*128 rows
#define Kk 256

// ---------------- scratch (static device memory; zero-initialized) ----------
__device__ float d_allf[(size_t)Tt*Dd];        // all_nodes fp32
__device__ __nv_bfloat16 d_Ahi[(size_t)TP*Kk];
__device__ __nv_bfloat16 d_Alo[(size_t)TP*Kk];
__device__ __nv_bfloat16 d_WmHi[Dd*Kk];        // head-mean of gat_W, transposed [n][k]
__device__ __nv_bfloat16 d_WmLo[Dd*Kk];
__device__ __nv_bfloat16 d_B2hi[Dd*Kk];        // gcn_W^T
__device__ __nv_bfloat16 d_B2lo[Dd*Kk];
__device__ float d_wsrc[Kk*Hh];                // gat_W @ att_src per head  [k][h]
__device__ float d_wdst[Kk*Hh];
__device__ float d_hmean[(size_t)TP*Dd];       // all_nodes @ Wm
__device__ float d_asrc[Tt*Hh];
__device__ float d_adst[Tt*Hh];
__device__ float d_w[128*Vv*520];              // softmax weights [bh][v][513]
__device__ float d_ypart[8*Bb*20*Dd];          // chunked weighted-x partials
__device__ float d_gvirtH[Bb*Vv*Hh*Dd];        // per-head virtual gat partials
__device__ __nv_bfloat16 d_G1hi[(size_t)TP*Kk];
__device__ __nv_bfloat16 d_G1lo[(size_t)TP*Kk];
__device__ float d_xw[(size_t)TP*Dd];
__device__ float d_S[Bb*Dd];

// ---------------- helpers ----------------------------------------------
__device__ __forceinline__ uint32_t smem_u32(const void* p) {
    uint32_t a;
    asm("{ .reg .u64 t; cvta.to.shared.u64 t, %1; cvt.u32.u64 %0, t; }"
        : "=r"(a) : "l"(p));
    return a;
}
__device__ __forceinline__ uint32_t sw64(uint32_t off) { return off ^ ((off >> 3) & 0x30); }

__device__ __forceinline__ void ldmx4(uint32_t* r, uint32_t addr) {
    asm volatile("ldmatrix.sync.aligned.m8n8.x4.shared.b16 {%0,%1,%2,%3}, [%4];"
                 : "=r"(r[0]), "=r"(r[1]), "=r"(r[2]), "=r"(r[3]) : "r"(addr));
}
__device__ __forceinline__ void mma16816(float* d, const uint32_t* a, uint32_t b0, uint32_t b1) {
    asm volatile(
        "mma.sync.aligned.m16n8k16.row.col.f32.bf16.bf16.f32 "
        "{%0,%1,%2,%3}, {%4,%5,%6,%7}, {%8,%9}, {%0,%1,%2,%3};"
        : "+f"(d[0]), "+f"(d[1]), "+f"(d[2]), "+f"(d[3])
        : "r"(a[0]), "r"(a[1]), "r"(a[2]), "r"(a[3]), "r"(b0), "r"(b1));
}
__device__ __forceinline__ void cp16(uint32_t smem_addr, const void* gptr) {
    asm volatile("cp.async.cg.shared.global [%0], [%1], 16;"
                 :: "r"(smem_addr), "l"(gptr));
}
__device__ __forceinline__ void cp_commit() {
    asm volatile("cp.async.commit_group;" ::: "memory");
}
__device__ __forceinline__ void cp_wait1() {
    asm volatile("cp.async.wait_group 1;" ::: "memory");
}
__device__ __forceinline__ void split_bf16(float v, __nv_bfloat16& hi, __nv_bfloat16& lo) {
    hi = __float2bfloat16(v);
    lo = __float2bfloat16(v - __bfloat162float(hi));
}

// ---------------- builders -----------------------------------------
// wsrc[k][h] = <gat_W[k, h*256: ], att_src[h]>, same for dst. 2048 warps.
__global__ void k_watt(const float* __restrict__ gat_W,
                       const float* __restrict__ att_src, const float* __restrict__ att_dst) {
    int gw = blockIdx.x * 8 + (threadIdx.x >> 5);   // 0..2047
    int lane = threadIdx.x & 31;
    int k = gw >> 3;
    int h = (gw >> 1) & 3;
    bool is_dst = gw & 1;
    const float* wp = gat_W + (size_t)k * 1024 + h * 256;
    const float* ap = (is_dst ? att_dst : att_src) + h * 256;
    float s = 0.f;
#pragma unroll
    for (int j = 0; j < 8; j++) s += wp[lane + 32 * j] * ap[lane + 32 * j];
#pragma unroll
    for (int o = 16; o; o >>= 1) s += __shfl_xor_sync(0xffffffffu, s, o);
    if (lane == 0) {
        if (is_dst) d_wdst[k * 4 + h] = s;
        else        d_wsrc[k * 4 + h] = s;
    }
}

// all_nodes build + bf16 split + fused attention scores (needs d_wsrc/d_wdst).
// grid Tt, 256 threads (one node per block).
__global__ void k_build(const float* __restrict__ x, const float* __restrict__ vn) {
    __shared__ float row[256];
    int t = blockIdx.x;
    int c = threadIdx.x;
    int idx = t * 256 + c;
    float v = (t < BN) ? x[idx] : vn[((t - BN) % Vv) * Dd + c];
    d_allf[idx] = v;
    __nv_bfloat16 hi, lo;
    split_bf16(v, hi, lo);
    d_Ahi[idx] = hi;
    d_Alo[idx] = lo;
    row[c] = v;
    __syncthreads();

    int w = c >> 5, lane = c & 31;
    int head = w >> 1;
    bool is_dst = (w & 1);
    const float* wp = (is_dst ? d_wdst : d_wsrc);
    float s = 0.f;
#pragma unroll
    for (int j = 0; j < 8; j++) {
        int k = lane + 32 * j;
        s += row[k] * wp[k * 4 + head];
    }
#pragma unroll
    for (int o = 16; o; o >>= 1) s += __shfl_xor_sync(0xffffffffu, s, o);
    if (lane == 0) {
        if (is_dst) d_adst[t * Hh + head] = s;
        else        d_asrc[t * Hh + head] = s;
    }
}

// Wm^T[n][k] = 0.25 * sum_h gat_W[k, h*256+n], split bf16
__global__ void k_wm(const float* __restrict__ gat_W) {
    int n = blockIdx.x;
    int k = threadIdx.x;
    const float* p = gat_W + (size_t)k * 1024 + n;
    float v = 0.25f * (p[0] + p[256] + p[512] + p[768]);
    __nv_bfloat16 hi, lo;
    split_bf16(v, hi, lo);
    d_WmHi[n * 256 + k] = hi;
    d_WmLo[n * 256 + k] = lo;
}

// transpose + split: gcn_W [256,256] -> Bt [n][k]
__global__ void k_cvt_bt(const float* __restrict__ B) {
    int idx = blockIdx.x * 256 + threadIdx.x;
    int n = idx >> 8;
    int k = idx & 255;
    float v = B[k * 256 + n];
    __nv_bfloat16 hi, lo;
    split_bf16(v, hi, lo);
    d_B2hi[idx] = hi;
    d_B2lo[idx] = lo;
}

// ---------------- pipelined mma.sync split-bf16 GEMM -----------------------
// C[TP, 256] = A[TP,256] * Bt[256,256]^T. grid (2, 130), 256 thr.
// 3-stage cp.async ring, 96KB. NO occupancy clamp (regs ~144, no spills).
#define NSTAGE 3
#define STAGE_BYTES 32768
#define OFF_AH 0
#define OFF_AL 8192
#define OFF_BH 16384
#define OFF_BL 24576

__global__ void __launch_bounds__(256) k_mma_gemm(
    const __nv_bfloat16* __restrict__ Ahi, const __nv_bfloat16* __restrict__ Alo,
    const __nv_bfloat16* __restrict__ Bhi, const __nv_bfloat16* __restrict__ Blo,
    float* __restrict__ C)
{
    extern __shared__ __align__(128) char smem[];
    const uint32_t sbase = smem_u32(smem);

    const int tid = threadIdx.x;
    const int wid = tid >> 5, lane = tid & 31;
    const int wm = (wid >> 2) * 64;
    const int wn = (wid & 3) * 32;
    const int mBase = blockIdx.y * 128;
    const int nBase = blockIdx.x * 128;

    const int lrow0 = tid >> 2;
    const int lc16  = tid & 3;
    const uint4* A4h = reinterpret_cast<const uint4*>(Ahi);
    const uint4* A4l = reinterpret_cast<const uint4*>(Alo);
    const uint4* B4h = reinterpret_cast<const uint4*>(Bhi);
    const uint4* B4l = reinterpret_cast<const uint4*>(Blo);

    float acc[4][4][4];
#pragma unroll
    for (int i = 0; i < 4; i++)
#pragma unroll
        for (int j = 0; j < 4; j++)
#pragma unroll
            for (int e = 0; e < 4; e++) acc[i][j][e] = 0.f;

    const uint32_t aRow = (uint32_t)((lane & 7) + (lane & 8));
    const uint32_t aColB = (lane & 16) ? 16u : 0u;
    const uint32_t bRow = (uint32_t)((lane & 7) + ((lane & 16) >> 1));
    const uint32_t bColB = (lane & 8) ? 16u : 0u;

    auto prefetch = [&](int kc) {
        uint32_t st = sbase + (kc % NSTAGE) * STAGE_BYTES;
#pragma unroll
        for (int q = 0; q < 2; q++) {
            int row = lrow0 + q * 64;
            uint32_t sw = sw64((uint32_t)(row * 64 + lc16 * 16));
            int ga = (mBase + row) * 32 + kc * 4 + lc16;
            int gb = (nBase + row) * 32 + kc * 4 + lc16;
            cp16(st + OFF_AH + sw, A4h + ga);
            cp16(st + OFF_AL + sw, A4l + ga);
            cp16(st + OFF_BH + sw, B4h + gb);
            cp16(st + OFF_BL + sw, B4l + gb);
        }
    };

    prefetch(0); cp_commit();
    prefetch(1); cp_commit();

    for (int kc = 0; kc < 8; kc++) {
        cp_wait1();                 // stage kc resident
        __syncthreads();
        if (kc + 2 < 8) prefetch(kc + 2);
        cp_commit();

        uint32_t st = sbase + (kc % NSTAGE) * STAGE_BYTES;
#pragma unroll
        for (int s = 0; s < 2; s++) {
            uint32_t bh[2][4], bl[2][4];
#pragma unroll
            for (int ng = 0; ng < 2; ng++) {
                uint32_t byteo = sw64((uint32_t)((wn + ng * 16 + bRow) * 64) + s * 32u + bColB);
                ldmx4(bh[ng], st + OFF_BH + byteo);
                ldmx4(bl[ng], st + OFF_BL + byteo);
            }
#pragma unroll
            for (int mt = 0; mt < 4; mt++) {
                uint32_t ah[4], al[4];
                uint32_t byteo = sw64((uint32_t)((wm + mt * 16 + aRow) * 64) + s * 32u + aColB);
                ldmx4(ah, st + OFF_AH + byteo);
                ldmx4(al, st + OFF_AL + byteo);
#pragma unroll
                for (int ng = 0; ng < 2; ng++) {
                    mma16816(acc[mt][ng * 2],     ah, bh[ng][0], bh[ng][1]);
                    mma16816(acc[mt][ng * 2 + 1], ah, bh[ng][2], bh[ng][3]);
                    mma16816(acc[mt][ng * 2],     ah, bl[ng][0], bl[ng][1]);
                    mma16816(acc[mt][ng * 2 + 1], ah, bl[ng][2], bl[ng][3]);
                    mma16816(acc[mt][ng * 2],     al, bh[ng][0], bh[ng][1]);
                    mma16816(acc[mt][ng * 2 + 1], al, bh[ng][2], bh[ng][3]);
                }
            }
        }
        __syncthreads();
    }

    int mThr = mBase + wm + (lane >> 2);
    int nThr = nBase + wn + (lane & 3) * 2;
#pragma unroll
    for (int mt = 0; mt < 4; mt++)
#pragma unroll
        for (int nt = 0; nt < 4; nt++) {
            int r0 = mThr + mt * 16;
            int cc = nThr + nt * 8;
            float2 v0 = make_float2(acc[mt][nt][0], acc[mt][nt][1]);
            float2 v1 = make_float2(acc[mt][nt][2], acc[mt][nt][3]);
            *reinterpret_cast<float2*>(C + (size_t)r0 * 256 + cc) = v0;
            *reinterpret_cast<float2*>(C + (size_t)(r0 + 8) * 256 + cc) = v1;
        }
}

__device__ __forceinline__ float lrelu(float x) { return x > 0.f ? x : 0.2f * x; }

// ---------------- softmax weights: one block per (b,head,v) -----------------
// grid 640: g = bh*5 + v
__global__ void k_vw() {
    int g = blockIdx.x;
    int bh = g / Vv, v = g % Vv;
    int b = bh >> 2, head = bh & 3;
    int tid = threadIdx.x;

    __shared__ float e_sh[Nn];
    __shared__ float red[256];

    int vt = BN + b * Vv + v;
    float adst = d_adst[vt * Hh + head];
    float aself = lrelu(d_asrc[vt * Hh + head] + adst);

    // alphas for real sources
    float a0 = lrelu(d_asrc[(b * Nn + tid) * Hh + head] + adst);
    float a1 = lrelu(d_asrc[(b * Nn + tid + 256) * Hh + head] + adst);

    // max
    float lm = fmaxf(fmaxf(a0, a1), aself);
    red[tid] = lm;
    __syncthreads();
    for (int s = 128; s > 0; s >>= 1) {
        if (tid < s) red[tid] = fmaxf(red[tid], red[tid + s]);
        __syncthreads();
    }
    float m = red[0];
    __syncthreads();

    // exp + sum
    float e0 = expf(a0 - m), e1 = expf(a1 - m);
    e_sh[tid] = e0;
    e_sh[tid + 256] = e1;
    float eS = expf(aself - m);
    float ls = e0 + e1 + ((tid == 0) ? eS : 0.f);
    red[tid] = ls;
    __syncthreads();
    for (int s = 128; s > 0; s >>= 1) {
        if (tid < s) red[tid] += red[tid + s];
        __syncthreads();
    }
    float inv = 1.f / red[0];

    float* wp = d_w + (size_t)g * 520;
    wp[tid] = e_sh[tid] * inv;
    wp[tid + 256] = e_sh[tid + 256] * inv;
    if (tid == 0) wp[512] = eS * inv;
}

// ---------------- weighted-x aggregation (chunked) --------------------------
// grid (32, 8): (batch, i-chunk of 64). block 256 = channel k.
__global__ void k_yagg() {
    int b = blockIdx.x;
    int chunk = blockIdx.y;
    int c = threadIdx.x;

    __shared__ float w_sh[20][64];
    for (int idx = c; idx < 20 * 64; idx += 256) {
        int vh = idx >> 6, ii = idx & 63;
        int v = vh >> 2, h = vh & 3;
        w_sh[vh][ii] = d_w[(size_t)((b * 4 + h) * Vv + v) * 520 + chunk * 64 + ii];
    }
    __syncthreads();

    float acc[20];
#pragma unroll
    for (int j = 0; j < 20; j++) acc[j] = 0.f;

    size_t base = (size_t)(b * Nn + chunk * 64) * Dd + c;
    for (int ii = 0; ii < 64; ii++) {
        float xv = d_allf[base + (size_t)ii * Dd];
#pragma unroll
        for (int j = 0; j < 20; j++) acc[j] += w_sh[j][ii] * xv;
    }
#pragma unroll
    for (int j = 0; j < 20; j++)
        d_ypart[(size_t)((chunk * Bb + b) * 20 + j) * Dd + c] = acc[j];
}

// ---------------- fused y-finalize + per-head virtual GEMM ------------------
// grid 640: g = bv*4 + h. gvirtH[g][c] = sum_k y[k] * gat_W[k, h*256+c]
__global__ void k_yv(const float* __restrict__ vn, const float* __restrict__ gat_W) {
    int g = blockIdx.x;
    int bv = g >> 2, h = g & 3;
    int b = bv / Vv, v = bv % Vv;
    int c = threadIdx.x;
    int vh = v * 4 + h;

    __shared__ float y[256];
    float s = 0.f;
#pragma unroll
    for (int chunk = 0; chunk < 8; chunk++)
        s += d_ypart[(size_t)((chunk * Bb + b) * 20 + vh) * Dd + c];
    s += d_w[(size_t)((b * 4 + h) * Vv + v) * 520 + 512] * vn[v * Dd + c];
    y[c] = s;
    __syncthreads();

    float acc = 0.f;
#pragma unroll 8
    for (int k = 0; k < 256; k++)
        acc += y[k] * gat_W[(size_t)k * 1024 + h * 256 + c];
    d_gvirtH[(size_t)g * Dd + c] = acc;
}

// ---------------- gelu + layernorm ----------------------------------
__device__ __forceinline__ float gelu_exact(float x) {
    return 0.5f * x * (1.f + erff(x * 0.70710678118654752f));
}
__device__ __forceinline__ float block_sum(float v, float* red) {
    int c = threadIdx.x;
    red[c] = v;
    __syncthreads();
    for (int s = 128; s > 0; s >>= 1) {
        if (c < s) red[c] += red[c + s];
        __syncthreads();
    }
    float r = red[0];
    __syncthreads();
    return r;
}

__global__ void k_norm1(const float* __restrict__ gat_bias,
                        const float* __restrict__ g, const float* __restrict__ bta) {
    __shared__ float red[256];
    int t = blockIdx.x;
    int c = threadIdx.x;
    float s;
    if (t < BN) {
        s = d_hmean[(size_t)t * Dd + c];
    } else {
        size_t base = (size_t)(t - BN) * 4 * Dd + c;
        s = 0.25f * (d_gvirtH[base] + d_gvirtH[base + Dd] +
                     d_gvirtH[base + 2 * Dd] + d_gvirtH[base + 3 * Dd]);
    }
    s += gat_bias[c];
    float ge = gelu_exact(s);
    float mean = block_sum(ge, red) * (1.f / Dd);
    float dlt = ge - mean;
    float var = block_sum(dlt * dlt, red) * (1.f / Dd);
    float val = dlt * rsqrtf(var + 1e-5f) * g[c] + bta[c];
    __nv_bfloat16 hi, lo;
    split_bf16(val, hi, lo);
    d_G1hi[(size_t)t * Dd + c] = hi;
    d_G1lo[(size_t)t * Dd + c] = lo;
}

__global__ void k_vsum() {
    int b = blockIdx.x;
    int c = threadIdx.x;
    float s = 0.f;
#pragma unroll
    for (int v = 0; v < Vv; v++)
        s += d_xw[(size_t)(BN + b * Vv + v) * Dd + c];
    d_S[b * Dd + c] = s;
}

__global__ void k_final(const float* __restrict__ gcn_bias,
                        const float* __restrict__ g, const float* __restrict__ bta,
                        float* __restrict__ out) {
    __shared__ float red[256];
    int t = blockIdx.x;
    int c = threadIdx.x;
    int b = t / Nn;
    const float inv_sqrt6 = 0.40824829046386301637f;
    const float inv6 = 0.16666666666666666667f;
    float u = inv_sqrt6 * d_S[b * Dd + c] + inv6 * d_xw[(size_t)t * Dd + c] + gcn_bias[c];
    float ge = gelu_exact(u);
    float mean = block_sum(ge, red) * (1.f / Dd);
    float dlt = ge - mean;
    float var = block_sum(dlt * dlt, red) * (1.f / Dd);
    out[(size_t)t * Dd + c] = dlt * rsqrtf(var + 1e-5f) * g[c] + bta[c];
}

// ---------------------------------------------------------------------------
extern "C" void kernel_launch(void* const* d_in, const int* in_sizes, int n_in,
                              void* d_out, int out_size) {
    const float* x        = (const float*)d_in[0];
    const float* vn       = (const float*)d_in[2];
    const float* gat_W    = (const float*)d_in[3];
    const float* att_src  = (const float*)d_in[4];
    const float* att_dst  = (const float*)d_in[5];
    const float* gat_bias = (const float*)d_in[6];
    const float* gcn_W    = (const float*)d_in[7];
    const float* gcn_bias = (const float*)d_in[8];
    const float* n1g      = (const float*)d_in[9];
    const float* n1b      = (const float*)d_in[10];
    const float* n2g      = (const float*)d_in[11];
    const float* n2b      = (const float*)d_in[12];
    float* out = (float*)d_out;

    const int SMEM_BYTES = NSTAGE * STAGE_BYTES;   // 96 KB
    cudaFuncSetAttribute(k_mma_gemm, cudaFuncAttributeMaxDynamicSharedMemorySize, SMEM_BYTES);

    __nv_bfloat16 *pAhi, *pAlo, *pWmHi, *pWmLo, *pB2hi, *pB2lo, *pG1hi, *pG1lo;
    float *pHM, *pXW;
    cudaGetSymbolAddress((void**)&pAhi,  d_Ahi);
    cudaGetSymbolAddress((void**)&pAlo,  d_Alo);
    cudaGetSymbolAddress((void**)&pWmHi, d_WmHi);
    cudaGetSymbolAddress((void**)&pWmLo, d_WmLo);
    cudaGetSymbolAddress((void**)&pB2hi, d_B2hi);
    cudaGetSymbolAddress((void**)&pB2lo, d_B2lo);
    cudaGetSymbolAddress((void**)&pG1hi, d_G1hi);
    cudaGetSymbolAddress((void**)&pG1lo, d_G1lo);
    cudaGetSymbolAddress((void**)&pHM,   d_hmean);
    cudaGetSymbolAddress((void**)&pXW,   d_xw);

    k_watt<<<256, 256>>>(gat_W, att_src, att_dst);
    k_wm<<<256, 256>>>(gat_W);
    k_cvt_bt<<<256, 256>>>(gcn_W);
    k_build<<<Tt, 256>>>(x, vn);     // also computes attention scores

    k_mma_gemm<<<dim3(2, TP / 128), 256, SMEM_BYTES>>>(pAhi, pAlo, pWmHi, pWmLo, pHM);

    k_vw<<<128 * Vv, 256>>>();
    k_yagg<<<dim3(Bb, 8), 256>>>();
    k_yv<<<Bb * Vv * Hh, 256>>>(vn, gat_W);
    k_norm1<<<Tt, 256>>>(gat_bias, n1g, n1b);

    k_mma_gemm<<<dim3(2, TP / 128), 256, SMEM_BYTES>>>(pG1hi, pG1lo, pB2hi, pB2lo, pXW);

    k_vsum<<<Bb, 256>>>();
    k_final<<<BN, 256>>>(gcn_bias, n2g, n2b, out);
}

// round 7
// speedup vs baseline: 2.1959x; 1.0103x over previous
#include <cuda_runtime.h>
#include <cuda_bf16.h>
#include <math.h>
#include <stdint.h>

#define Bb 32
#define Nn 512
#define Vv 5
#define Dd 256
#define Hh 4
#define BN (Bb*Nn)            // 16384 real nodes
#define Tt (BN + Bb*Vv)       // 16544 total nodes
#define TP 16640              // padded to 130*128 rows
#define Kk 256

// ---------------- scratch ----------------------------------------------------
__device__ float d_allf[(size_t)Tt*Dd];        // all_nodes fp32
__device__ __nv_bfloat16 d_Ahi[(size_t)TP*Kk];
__device__ __nv_bfloat16 d_Alo[(size_t)TP*Kk];
__device__ __nv_bfloat16 d_WmHi[Dd*Kk];        // head-mean of gat_W, transposed
__device__ __nv_bfloat16 d_WmLo[Dd*Kk];
__device__ __nv_bfloat16 d_B2hi[Dd*Kk];        // gcn_W^T
__device__ __nv_bfloat16 d_B2lo[Dd*Kk];
__device__ float d_wsrc[Kk*Hh];                // [k][h]
__device__ float d_wdst[Kk*Hh];
__device__ float d_hmean[(size_t)TP*Dd];
__device__ float d_asrc[Hh*Tt];                // [head][t]  (transposed!)
__device__ float d_adst[Hh*Tt];
__device__ float d_w[128*Vv*520];              // softmax weights [bh*5+v][513]
__device__ float d_ypart[8*Bb*20*Dd];
__device__ float d_gvirtH[Bb*Vv*Hh*Dd];        // [(bv)*4+h][c]
__device__ __nv_bfloat16 d_G1hi[(size_t)TP*Kk];
__device__ __nv_bfloat16 d_G1lo[(size_t)TP*Kk];
__device__ float d_xw[(size_t)TP*Dd];
__device__ float d_S[Bb*Dd];

// ---------------- helpers ----------------------------------------------------
__device__ __forceinline__ uint32_t smem_u32(const void* p) {
    uint32_t a;
    asm("{ .reg .u64 t; cvta.to.shared.u64 t, %1; cvt.u32.u64 %0, t; }"
        : "=r"(a) : "l"(p));
    return a;
}
__device__ __forceinline__ uint32_t sw64(uint32_t off) { return off ^ ((off >> 3) & 0x30); }

__device__ __forceinline__ void ldmx4(uint32_t* r, uint32_t addr) {
    asm volatile("ldmatrix.sync.aligned.m8n8.x4.shared.b16 {%0,%1,%2,%3}, [%4];"
                 : "=r"(r[0]), "=r"(r[1]), "=r"(r[2]), "=r"(r[3]) : "r"(addr));
}
__device__ __forceinline__ void mma16816(float* d, const uint32_t* a, uint32_t b0, uint32_t b1) {
    asm volatile(
        "mma.sync.aligned.m16n8k16.row.col.f32.bf16.bf16.f32 "
        "{%0,%1,%2,%3}, {%4,%5,%6,%7}, {%8,%9}, {%0,%1,%2,%3};"
        : "+f"(d[0]), "+f"(d[1]), "+f"(d[2]), "+f"(d[3])
        : "r"(a[0]), "r"(a[1]), "r"(a[2]), "r"(a[3]), "r"(b0), "r"(b1));
}
__device__ __forceinline__ void cp16(uint32_t smem_addr, const void* gptr) {
    asm volatile("cp.async.cg.shared.global [%0], [%1], 16;"
                 :: "r"(smem_addr), "l"(gptr));
}
__device__ __forceinline__ void cp_commit() {
    asm volatile("cp.async.commit_group;" ::: "memory");
}
__device__ __forceinline__ void cp_wait2() {
    asm volatile("cp.async.wait_group 2;" ::: "memory");
}
__device__ __forceinline__ void split_bf16(float v, __nv_bfloat16& hi, __nv_bfloat16& lo) {
    hi = __float2bfloat16(v);
    lo = __float2bfloat16(v - __bfloat162float(hi));
}
__device__ __forceinline__ uint32_t pack2(__nv_bfloat16 a, __nv_bfloat16 b) {
    return (uint32_t)__bfloat16_as_ushort(a) | ((uint32_t)__bfloat16_as_ushort(b) << 16);
}

// ---------------- fused prep: watt + wm + cvt_bt (one launch) ----------------
__global__ void k_prep(const float* __restrict__ gat_W,
                       const float* __restrict__ att_src, const float* __restrict__ att_dst,
                       const float* __restrict__ gcn_W) {
    int bid = blockIdx.x;
    int tid = threadIdx.x;
    if (bid < 256) {
        // wsrc[k][h] = <gat_W[k, h*256:], att[h]>; 8 warps per block
        int gw = bid * 8 + (tid >> 5);       // 0..2047
        int lane = tid & 31;
        int k = gw >> 3;
        int h = (gw >> 1) & 3;
        bool is_dst = gw & 1;
        const float* wp = gat_W + (size_t)k * 1024 + h * 256;
        const float* ap = (is_dst ? att_dst : att_src) + h * 256;
        float s = 0.f;
#pragma unroll
        for (int j = 0; j < 8; j++) s += wp[lane + 32 * j] * ap[lane + 32 * j];
#pragma unroll
        for (int o = 16; o; o >>= 1) s += __shfl_xor_sync(0xffffffffu, s, o);
        if (lane == 0) {
            if (is_dst) d_wdst[k * 4 + h] = s;
            else        d_wsrc[k * 4 + h] = s;
        }
    } else if (bid < 512) {
        // Wm^T[n][k] = 0.25 * sum_h gat_W[k, h*256+n]
        int n = bid - 256;
        int k = tid;
        const float* p = gat_W + (size_t)k * 1024 + n;
        float v = 0.25f * (p[0] + p[256] + p[512] + p[768]);
        __nv_bfloat16 hi, lo;
        split_bf16(v, hi, lo);
        d_WmHi[n * 256 + k] = hi;
        d_WmLo[n * 256 + k] = lo;
    } else {
        // gcn_W^T split
        int idx = (bid - 512) * 256 + tid;
        int n = idx >> 8;
        int k = idx & 255;
        float v = gcn_W[k * 256 + n];
        __nv_bfloat16 hi, lo;
        split_bf16(v, hi, lo);
        d_B2hi[idx] = hi;
        d_B2lo[idx] = lo;
    }
}

// ---------------- build: warp-per-node, vectorized, fused scores -------------
// grid Tt/8 = 2068 blocks, 256 threads (8 warps = 8 nodes).
__global__ void __launch_bounds__(256) k_build(const float* __restrict__ x,
                                               const float* __restrict__ vn) {
    __shared__ float ws[8][256];   // rows 0..3 = src h0..3, 4..7 = dst h0..3
    int tid = threadIdx.x;
#pragma unroll
    for (int i = 0; i < 8; i++) {
        int idx = tid + i * 256;           // < 2048
        int r = idx >> 8, k = idx & 255;
        ws[r][k] = (r < 4) ? d_wsrc[k * 4 + r] : d_wdst[k * 4 + (r & 3)];
    }
    __syncthreads();

    int w = tid >> 5, lane = tid & 31;
    int t = blockIdx.x * 8 + w;
    const float* src = (t < BN) ? (x + (size_t)t * Dd)
                                : (vn + (size_t)((t - BN) % Vv) * Dd);
    float4 f0 = *reinterpret_cast<const float4*>(src + 4 * lane);
    float4 f1 = *reinterpret_cast<const float4*>(src + 128 + 4 * lane);

    float4* allf4 = reinterpret_cast<float4*>(d_allf + (size_t)t * Dd);
    allf4[lane] = f0;
    allf4[lane + 32] = f1;

    // bf16 split, vector stores
    __nv_bfloat16 h[8], l[8];
    split_bf16(f0.x, h[0], l[0]); split_bf16(f0.y, h[1], l[1]);
    split_bf16(f0.z, h[2], l[2]); split_bf16(f0.w, h[3], l[3]);
    split_bf16(f1.x, h[4], l[4]); split_bf16(f1.y, h[5], l[5]);
    split_bf16(f1.z, h[6], l[6]); split_bf16(f1.w, h[7], l[7]);
    uint2* Ahi2 = reinterpret_cast<uint2*>(d_Ahi + (size_t)t * Dd);
    uint2* Alo2 = reinterpret_cast<uint2*>(d_Alo + (size_t)t * Dd);
    Ahi2[lane]      = make_uint2(pack2(h[0], h[1]), pack2(h[2], h[3]));
    Ahi2[lane + 32] = make_uint2(pack2(h[4], h[5]), pack2(h[6], h[7]));
    Alo2[lane]      = make_uint2(pack2(l[0], l[1]), pack2(l[2], l[3]));
    Alo2[lane + 32] = make_uint2(pack2(l[4], l[5]), pack2(l[6], l[7]));

    // attention scores: s[r] = <row, ws[r]>
    float s[8];
#pragma unroll
    for (int r = 0; r < 8; r++) {
        const float4* wr = reinterpret_cast<const float4*>(ws[r]);
        float4 w0 = wr[lane], w1 = wr[lane + 32];
        s[r] = f0.x * w0.x + f0.y * w0.y + f0.z * w0.z + f0.w * w0.w
             + f1.x * w1.x + f1.y * w1.y + f1.z * w1.z + f1.w * w1.w;
    }
#pragma unroll
    for (int o = 16; o; o >>= 1)
#pragma unroll
        for (int r = 0; r < 8; r++) s[r] += __shfl_xor_sync(0xffffffffu, s[r], o);

    if (lane < 4)      d_asrc[lane * Tt + t] = s[lane];
    else if (lane < 8) d_adst[(lane - 4) * Tt + t] = s[lane];
}

// ---------------- pipelined mma.sync split-bf16 GEMM -------------------------
// 4-stage cp.async ring (128KB), wait_group 2.
#define NSTAGE 4
#define STAGE_BYTES 32768
#define OFF_AH 0
#define OFF_AL 8192
#define OFF_BH 16384
#define OFF_BL 24576

__global__ void __launch_bounds__(256) k_mma_gemm(
    const __nv_bfloat16* __restrict__ Ahi, const __nv_bfloat16* __restrict__ Alo,
    const __nv_bfloat16* __restrict__ Bhi, const __nv_bfloat16* __restrict__ Blo,
    float* __restrict__ C)
{
    extern __shared__ __align__(128) char smem[];
    const uint32_t sbase = smem_u32(smem);

    const int tid = threadIdx.x;
    const int wid = tid >> 5, lane = tid & 31;
    const int wm = (wid >> 2) * 64;
    const int wn = (wid & 3) * 32;
    const int mBase = blockIdx.y * 128;
    const int nBase = blockIdx.x * 128;

    const int lrow0 = tid >> 2;
    const int lc16  = tid & 3;
    const uint4* A4h = reinterpret_cast<const uint4*>(Ahi);
    const uint4* A4l = reinterpret_cast<const uint4*>(Alo);
    const uint4* B4h = reinterpret_cast<const uint4*>(Bhi);
    const uint4* B4l = reinterpret_cast<const uint4*>(Blo);

    float acc[4][4][4];
#pragma unroll
    for (int i = 0; i < 4; i++)
#pragma unroll
        for (int j = 0; j < 4; j++)
#pragma unroll
            for (int e = 0; e < 4; e++) acc[i][j][e] = 0.f;

    const uint32_t aRow = (uint32_t)((lane & 7) + (lane & 8));
    const uint32_t aColB = (lane & 16) ? 16u : 0u;
    const uint32_t bRow = (uint32_t)((lane & 7) + ((lane & 16) >> 1));
    const uint32_t bColB = (lane & 8) ? 16u : 0u;

    auto prefetch = [&](int kc) {
        uint32_t st = sbase + (kc & (NSTAGE - 1)) * STAGE_BYTES;
#pragma unroll
        for (int q = 0; q < 2; q++) {
            int row = lrow0 + q * 64;
            uint32_t sw = sw64((uint32_t)(row * 64 + lc16 * 16));
            int ga = (mBase + row) * 32 + kc * 4 + lc16;
            int gb = (nBase + row) * 32 + kc * 4 + lc16;
            cp16(st + OFF_AH + sw, A4h + ga);
            cp16(st + OFF_AL + sw, A4l + ga);
            cp16(st + OFF_BH + sw, B4h + gb);
            cp16(st + OFF_BL + sw, B4l + gb);
        }
    };

    prefetch(0); cp_commit();
    prefetch(1); cp_commit();
    prefetch(2); cp_commit();

    for (int kc = 0; kc < 8; kc++) {
        cp_wait2();                 // stage kc resident (<=2 groups outstanding)
        __syncthreads();            // also guards ring-slot reuse
        if (kc + 3 < 8) prefetch(kc + 3);
        cp_commit();

        uint32_t st = sbase + (kc & (NSTAGE - 1)) * STAGE_BYTES;
#pragma unroll
        for (int s = 0; s < 2; s++) {
            uint32_t bh[2][4], bl[2][4];
#pragma unroll
            for (int ng = 0; ng < 2; ng++) {
                uint32_t byteo = sw64((uint32_t)((wn + ng * 16 + bRow) * 64) + s * 32u + bColB);
                ldmx4(bh[ng], st + OFF_BH + byteo);
                ldmx4(bl[ng], st + OFF_BL + byteo);
            }
#pragma unroll
            for (int mt = 0; mt < 4; mt++) {
                uint32_t ah[4], al[4];
                uint32_t byteo = sw64((uint32_t)((wm + mt * 16 + aRow) * 64) + s * 32u + aColB);
                ldmx4(ah, st + OFF_AH + byteo);
                ldmx4(al, st + OFF_AL + byteo);
#pragma unroll
                for (int ng = 0; ng < 2; ng++) {
                    mma16816(acc[mt][ng * 2],     ah, bh[ng][0], bh[ng][1]);
                    mma16816(acc[mt][ng * 2 + 1], ah, bh[ng][2], bh[ng][3]);
                    mma16816(acc[mt][ng * 2],     ah, bl[ng][0], bl[ng][1]);
                    mma16816(acc[mt][ng * 2 + 1], ah, bl[ng][2], bl[ng][3]);
                    mma16816(acc[mt][ng * 2],     al, bh[ng][0], bh[ng][1]);
                    mma16816(acc[mt][ng * 2 + 1], al, bh[ng][2], bh[ng][3]);
                }
            }
        }
    }

    int mThr = mBase + wm + (lane >> 2);
    int nThr = nBase + wn + (lane & 3) * 2;
#pragma unroll
    for (int mt = 0; mt < 4; mt++)
#pragma unroll
        for (int nt = 0; nt < 4; nt++) {
            int r0 = mThr + mt * 16;
            int cc = nThr + nt * 8;
            float2 v0 = make_float2(acc[mt][nt][0], acc[mt][nt][1]);
            float2 v1 = make_float2(acc[mt][nt][2], acc[mt][nt][3]);
            *reinterpret_cast<float2*>(C + (size_t)r0 * 256 + cc) = v0;
            *reinterpret_cast<float2*>(C + (size_t)(r0 + 8) * 256 + cc) = v1;
        }
}

__device__ __forceinline__ float lrelu(float x) { return x > 0.f ? x : 0.2f * x; }

// ---------------- softmax weights: one block per (b,head,v) ------------------
__global__ void k_vw() {
    int g = blockIdx.x;                // bh*5 + v
    int bh = g / Vv, v = g % Vv;
    int b = bh >> 2, head = bh & 3;
    int tid = threadIdx.x;

    __shared__ float e_sh[Nn];
    __shared__ float red[256];

    int vt = BN + b * Vv + v;
    float adst = d_adst[head * Tt + vt];
    float aself = lrelu(d_asrc[head * Tt + vt] + adst);

    const float* ap = d_asrc + head * Tt + b * Nn;
    float a0 = lrelu(ap[tid] + adst);
    float a1 = lrelu(ap[tid + 256] + adst);

    float lm = fmaxf(fmaxf(a0, a1), aself);
    red[tid] = lm;
    __syncthreads();
    for (int s = 128; s > 0; s >>= 1) {
        if (tid < s) red[tid] = fmaxf(red[tid], red[tid + s]);
        __syncthreads();
    }
    float m = red[0];
    __syncthreads();

    float e0 = expf(a0 - m), e1 = expf(a1 - m);
    e_sh[tid] = e0;
    e_sh[tid + 256] = e1;
    float eS = expf(aself - m);
    float ls = e0 + e1 + ((tid == 0) ? eS : 0.f);
    red[tid] = ls;
    __syncthreads();
    for (int s = 128; s > 0; s >>= 1) {
        if (tid < s) red[tid] += red[tid + s];
        __syncthreads();
    }
    float inv = 1.f / red[0];

    float* wp = d_w + (size_t)g * 520;
    wp[tid] = e_sh[tid] * inv;
    wp[tid + 256] = e_sh[tid + 256] * inv;
    if (tid == 0) wp[512] = eS * inv;
}

// ---------------- weighted-x aggregation (chunked) ---------------------------
__global__ void k_yagg() {
    int b = blockIdx.x;
    int chunk = blockIdx.y;
    int c = threadIdx.x;

    __shared__ float w_sh[20][64];
    for (int idx = c; idx < 20 * 64; idx += 256) {
        int vh = idx >> 6, ii = idx & 63;
        int v = vh >> 2, h = vh & 3;
        w_sh[vh][ii] = d_w[(size_t)((b * 4 + h) * Vv + v) * 520 + chunk * 64 + ii];
    }
    __syncthreads();

    float acc[20];
#pragma unroll
    for (int j = 0; j < 20; j++) acc[j] = 0.f;

    size_t base = (size_t)(b * Nn + chunk * 64) * Dd + c;
    for (int ii = 0; ii < 64; ii++) {
        float xv = d_allf[base + (size_t)ii * Dd];
#pragma unroll
        for (int j = 0; j < 20; j++) acc[j] += w_sh[j][ii] * xv;
    }
#pragma unroll
    for (int j = 0; j < 20; j++)
        d_ypart[(size_t)((chunk * Bb + b) * 20 + j) * Dd + c] = acc[j];
}

// ---------------- y-finalize + virtual GEMM, (b,h)-blocked -------------------
// grid 128: g = b*4 + h. Reads gat_W head-block once for all 5 v's.
__global__ void k_yv(const float* __restrict__ vn, const float* __restrict__ gat_W) {
    int g = blockIdx.x;
    int b = g >> 2, h = g & 3;
    int c = threadIdx.x;

    __shared__ float y[Vv][256];
#pragma unroll
    for (int v = 0; v < Vv; v++) {
        float s = 0.f;
        int vh = v * 4 + h;
#pragma unroll
        for (int chunk = 0; chunk < 8; chunk++)
            s += d_ypart[(size_t)((chunk * Bb + b) * 20 + vh) * Dd + c];
        s += d_w[(size_t)((b * 4 + h) * Vv + v) * 520 + 512] * vn[v * Dd + c];
        y[v][c] = s;
    }
    __syncthreads();

    float acc[Vv] = {0.f, 0.f, 0.f, 0.f, 0.f};
    const float* wcol = gat_W + h * 256 + c;
#pragma unroll 4
    for (int k = 0; k < 256; k++) {
        float wv = wcol[(size_t)k * 1024];
#pragma unroll
        for (int v = 0; v < Vv; v++) acc[v] += y[v][k] * wv;
    }
#pragma unroll
    for (int v = 0; v < Vv; v++)
        d_gvirtH[(size_t)(((b * Vv + v) * 4) + h) * Dd + c] = acc[v];
}

// ---------------- gelu + layernorm -------------------------------------------
__device__ __forceinline__ float gelu_exact(float x) {
    return 0.5f * x * (1.f + erff(x * 0.70710678118654752f));
}
__device__ __forceinline__ float block_sum(float v, float* red) {
    int c = threadIdx.x;
    red[c] = v;
    __syncthreads();
    for (int s = 128; s > 0; s >>= 1) {
        if (c < s) red[c] += red[c + s];
        __syncthreads();
    }
    float r = red[0];
    __syncthreads();
    return r;
}

__global__ void k_norm1(const float* __restrict__ gat_bias,
                        const float* __restrict__ g, const float* __restrict__ bta) {
    __shared__ float red[256];
    int t = blockIdx.x;
    int c = threadIdx.x;
    float s;
    if (t < BN) {
        s = d_hmean[(size_t)t * Dd + c];
    } else {
        size_t base = (size_t)(t - BN) * 4 * Dd + c;
        s = 0.25f * (d_gvirtH[base] + d_gvirtH[base + Dd] +
                     d_gvirtH[base + 2 * Dd] + d_gvirtH[base + 3 * Dd]);
    }
    s += gat_bias[c];
    float ge = gelu_exact(s);
    float mean = block_sum(ge, red) * (1.f / Dd);
    float dlt = ge - mean;
    float var = block_sum(dlt * dlt, red) * (1.f / Dd);
    float val = dlt * rsqrtf(var + 1e-5f) * g[c] + bta[c];
    __nv_bfloat16 hi, lo;
    split_bf16(val, hi, lo);
    d_G1hi[(size_t)t * Dd + c] = hi;
    d_G1lo[(size_t)t * Dd + c] = lo;
}

__global__ void k_vsum() {
    int b = blockIdx.x;
    int c = threadIdx.x;
    float s = 0.f;
#pragma unroll
    for (int v = 0; v < Vv; v++)
        s += d_xw[(size_t)(BN + b * Vv + v) * Dd + c];
    d_S[b * Dd + c] = s;
}

__global__ void k_final(const float* __restrict__ gcn_bias,
                        const float* __restrict__ g, const float* __restrict__ bta,
                        float* __restrict__ out) {
    __shared__ float red[256];
    int t = blockIdx.x;
    int c = threadIdx.x;
    int b = t / Nn;
    const float inv_sqrt6 = 0.40824829046386301637f;
    const float inv6 = 0.16666666666666666667f;
    float u = inv_sqrt6 * d_S[b * Dd + c] + inv6 * d_xw[(size_t)t * Dd + c] + gcn_bias[c];
    float ge = gelu_exact(u);
    float mean = block_sum(ge, red) * (1.f / Dd);
    float dlt = ge - mean;
    float var = block_sum(dlt * dlt, red) * (1.f / Dd);
    out[(size_t)t * Dd + c] = dlt * rsqrtf(var + 1e-5f) * g[c] + bta[c];
}

// -----------------------------------------------------------------------------
extern "C" void kernel_launch(void* const* d_in, const int* in_sizes, int n_in,
                              void* d_out, int out_size) {
    const float* x        = (const float*)d_in[0];
    const float* vn       = (const float*)d_in[2];
    const float* gat_W    = (const float*)d_in[3];
    const float* att_src  = (const float*)d_in[4];
    const float* att_dst  = (const float*)d_in[5];
    const float* gat_bias = (const float*)d_in[6];
    const float* gcn_W    = (const float*)d_in[7];
    const float* gcn_bias = (const float*)d_in[8];
    const float* n1g      = (const float*)d_in[9];
    const float* n1b      = (const float*)d_in[10];
    const float* n2g      = (const float*)d_in[11];
    const float* n2b      = (const float*)d_in[12];
    float* out = (float*)d_out;

    const int SMEM_BYTES = NSTAGE * STAGE_BYTES;   // 128 KB
    cudaFuncSetAttribute(k_mma_gemm, cudaFuncAttributeMaxDynamicSharedMemorySize, SMEM_BYTES);

    __nv_bfloat16 *pAhi, *pAlo, *pWmHi, *pWmLo, *pB2hi, *pB2lo, *pG1hi, *pG1lo;
    float *pHM, *pXW;
    cudaGetSymbolAddress((void**)&pAhi,  d_Ahi);
    cudaGetSymbolAddress((void**)&pAlo,  d_Alo);
    cudaGetSymbolAddress((void**)&pWmHi, d_WmHi);
    cudaGetSymbolAddress((void**)&pWmLo, d_WmLo);
    cudaGetSymbolAddress((void**)&pB2hi, d_B2hi);
    cudaGetSymbolAddress((void**)&pB2lo, d_B2lo);
    cudaGetSymbolAddress((void**)&pG1hi, d_G1hi);
    cudaGetSymbolAddress((void**)&pG1lo, d_G1lo);
    cudaGetSymbolAddress((void**)&pHM,   d_hmean);
    cudaGetSymbolAddress((void**)&pXW,   d_xw);

    k_prep<<<768, 256>>>(gat_W, att_src, att_dst, gcn_W);
    k_build<<<Tt / 8, 256>>>(x, vn);

    k_mma_gemm<<<dim3(2, TP / 128), 256, SMEM_BYTES>>>(pAhi, pAlo, pWmHi, pWmLo, pHM);

    k_vw<<<128 * Vv, 256>>>();
    k_yagg<<<dim3(Bb, 8), 256>>>();
    k_yv<<<Bb * Hh, 256>>>(vn, gat_W);
    k_norm1<<<Tt, 256>>>(gat_bias, n1g, n1b);

    k_mma_gemm<<<dim3(2, TP / 128), 256, SMEM_BYTES>>>(pG1hi, pG1lo, pB2hi, pB2lo, pXW);

    k_vsum<<<Bb, 256>>>();
    k_final<<<BN, 256>>>(gcn_bias, n2g, n2b, out);
}